// round 11
// baseline (speedup 1.0000x reference)
#include <cuda_runtime.h>
#include <cuda_bf16.h>
#include <cstdint>
#include <math.h>

// ---------------- problem constants ----------------
#define BZ   2
#define SQ   2048
#define HIDN 1024
#define NHD  16
#define HDIM 64
#define MROWS (BZ * SQ)      // 4096
#define WIN  64              // LOCAL_WINDOW / 2

// ---------------- scratch (no allocations allowed) ----------------
__device__ float g_Q[MROWS * HIDN];
__device__ float g_K[MROWS * HIDN];
__device__ float g_V[MROWS * HIDN];
__device__ __nv_bfloat16 g_Xh[MROWS * HIDN];
__device__ __nv_bfloat16 g_Xl[MROWS * HIDN];
__device__ __nv_bfloat16 g_Oh[MROWS * HIDN];
__device__ __nv_bfloat16 g_Ol[MROWS * HIDN];
__device__ __nv_bfloat16 g_Wh[4][HIDN * HIDN];
__device__ __nv_bfloat16 g_Wl[4][HIDN * HIDN];

// ================= helpers =================
__device__ __forceinline__ uint32_t smem_u32(const void* p) {
    uint32_t a;
    asm("{ .reg .u64 t; cvta.to.shared.u64 t, %1; cvt.u32.u64 %0, t; }" : "=r"(a) : "l"(p));
    return a;
}
#define CP_ASYNC16(sm, gm) \
    asm volatile("cp.async.cg.shared.global [%0], [%1], 16;" :: "r"(sm), "l"(gm) : "memory")
#define CP_COMMIT() asm volatile("cp.async.commit_group;" ::: "memory")
#define CP_WAIT2()  asm volatile("cp.async.wait_group 2;" ::: "memory")

#define LDSM_X4(r0, r1, r2, r3, addr) \
    asm volatile("ldmatrix.sync.aligned.m8n8.x4.shared.b16 {%0,%1,%2,%3}, [%4];" \
        : "=r"(r0), "=r"(r1), "=r"(r2), "=r"(r3) : "r"(addr))

#define MMA_BF16(d, a, b) \
    asm volatile("mma.sync.aligned.m16n8k16.row.col.f32.bf16.bf16.f32 " \
        "{%0,%1,%2,%3}, {%4,%5,%6,%7}, {%8,%9}, {%0,%1,%2,%3};" \
        : "+f"((d)[0]), "+f"((d)[1]), "+f"((d)[2]), "+f"((d)[3]) \
        : "r"((a)[0]), "r"((a)[1]), "r"((a)[2]), "r"((a)[3]), "r"((b)[0]), "r"((b)[1]))

// ================= fp32 -> (bf16 hi, bf16 lo) split =================
__device__ __forceinline__ void split4(const float* __restrict__ src,
                                       __nv_bfloat16* __restrict__ hi,
                                       __nv_bfloat16* __restrict__ lo, int i) {
    float4 v = reinterpret_cast<const float4*>(src)[i];
    __nv_bfloat16 h0 = __float2bfloat16(v.x), h1 = __float2bfloat16(v.y);
    __nv_bfloat16 h2 = __float2bfloat16(v.z), h3 = __float2bfloat16(v.w);
    __nv_bfloat16 l0 = __float2bfloat16(v.x - __bfloat162float(h0));
    __nv_bfloat16 l1 = __float2bfloat16(v.y - __bfloat162float(h1));
    __nv_bfloat16 l2 = __float2bfloat16(v.z - __bfloat162float(h2));
    __nv_bfloat16 l3 = __float2bfloat16(v.w - __bfloat162float(h3));
    __nv_bfloat162 hA = __halves2bfloat162(h0, h1), hB = __halves2bfloat162(h2, h3);
    __nv_bfloat162 lA = __halves2bfloat162(l0, l1), lB = __halves2bfloat162(l2, l3);
    uint2 ho, lout;
    ho.x = *reinterpret_cast<uint32_t*>(&hA); ho.y = *reinterpret_cast<uint32_t*>(&hB);
    lout.x = *reinterpret_cast<uint32_t*>(&lA); lout.y = *reinterpret_cast<uint32_t*>(&lB);
    reinterpret_cast<uint2*>(hi)[i] = ho;
    reinterpret_cast<uint2*>(lo)[i] = lout;
}

__global__ __launch_bounds__(256) void split_kernel(const float* __restrict__ src,
                                                    __nv_bfloat16* __restrict__ hi,
                                                    __nv_bfloat16* __restrict__ lo, int n4) {
    int i = blockIdx.x * 256 + threadIdx.x;
    if (i < n4) split4(src, hi, lo, i);
}

__global__ __launch_bounds__(256) void split_w_kernel(
    const float* __restrict__ w0, const float* __restrict__ w1,
    const float* __restrict__ w2, const float* __restrict__ w3,
    __nv_bfloat16* __restrict__ hiBase, __nv_bfloat16* __restrict__ loBase)
{
    const int which = blockIdx.y;
    const float* src = (which == 0) ? w0 : (which == 1) ? w1 : (which == 2) ? w2 : w3;
    __nv_bfloat16* hi = hiBase + (size_t)which * HIDN * HIDN;
    __nv_bfloat16* lo = loBase + (size_t)which * HIDN * HIDN;
    int i = blockIdx.x * 256 + threadIdx.x;
    if (i < HIDN * HIDN / 4) split4(src, hi, lo, i);
}

// ================= mma.sync bf16x3 GEMM, fused terms, 4-stage BK=16 ring =================
// 128x128 CTA tile, 256 threads = 8 warps (2 row x 4 col), warp tile 64x32.
// Each 16-k stage holds Ah/Al/Bh/Bl; issues Ah*Bh + Ah*Bl + Al*Bh from registers.
// 4-stage ring -> refill target never the live buffer -> ONE sync/stage, 2 stages prefetch.
#define GPITCH_B 48u          // bytes per smem row (32B data + 16B pad; 3 coprime 8 -> conflict-free)
#define MBUFB    6144u        // one matrix per stage: 128 * 48
#define GSTGB    24576u       // 4 matrices per stage
#define NSTAGE   4
#define GSTAGES  64           // 1024 / 16
#define GEMM_SMEM (NSTAGE * GSTGB)   // 98304

__global__ __launch_bounds__(256, 2) void gemm_mma_kernel(
    const __nv_bfloat16* __restrict__ Ah, const __nv_bfloat16* __restrict__ Al,
    const __nv_bfloat16* __restrict__ Whb, const __nv_bfloat16* __restrict__ Wlb,
    int wbase,
    const float* __restrict__ b0, const float* __restrict__ b1, const float* __restrict__ b2,
    float* __restrict__ C0, float* __restrict__ C1, float* __restrict__ C2)
{
    extern __shared__ __align__(16) char gsm[];

    const int z = blockIdx.z;
    const __nv_bfloat16* Bh = Whb + (size_t)(wbase + z) * HIDN * HIDN;
    const __nv_bfloat16* Bl = Wlb + (size_t)(wbase + z) * HIDN * HIDN;
    const float* bias = (z == 0) ? b0 : (z == 1) ? b1 : b2;
    float* C = (z == 0) ? C0 : (z == 1) ? C1 : C2;

    const int tid = threadIdx.x;
    const int wid = tid >> 5;
    const int lane = tid & 31;
    const int wm = wid & 1;          // warp row 0..1 (64 rows each)
    const int wn = wid >> 1;         // warp col 0..3 (32 cols each)
    const int m0 = blockIdx.y * 128;
    const int n0 = blockIdx.x * 128;

    const uint32_t smBase = smem_u32(gsm);

    float acc[4][4][4];
    #pragma unroll
    for (int mi = 0; mi < 4; ++mi)
        #pragma unroll
        for (int j = 0; j < 4; ++j)
            #pragma unroll
            for (int r = 0; r < 4; ++r) acc[mi][j][r] = 0.f;

    // stage load: 4 matrices x 128 rows x 32B; one 16B chunk per thread per matrix
    const int lr = tid >> 1;          // row 0..127
    const int lc = tid & 1;           // chunk 0..1
    auto issue_stage = [&](int s) {
        const int kk = s << 4;
        const uint32_t sbase = smBase + (uint32_t)(s & (NSTAGE - 1)) * GSTGB;
        const uint32_t so = (uint32_t)lr * GPITCH_B + (uint32_t)lc * 16u;
        const size_t ga = (size_t)(m0 + lr) * HIDN + kk + lc * 8;
        const size_t gb = (size_t)(n0 + lr) * HIDN + kk + lc * 8;
        CP_ASYNC16(sbase + so,             Ah + ga);
        CP_ASYNC16(sbase + MBUFB + so,     Al + ga);
        CP_ASYNC16(sbase + 2 * MBUFB + so, Bh + gb);
        CP_ASYNC16(sbase + 3 * MBUFB + so, Bl + gb);
    };

    issue_stage(0); CP_COMMIT();
    issue_stage(1); CP_COMMIT();
    issue_stage(2); CP_COMMIT();

    const uint32_t aFragOff = (uint32_t)((wm * 64 + (lane & 15)) * GPITCH_B + ((lane >> 4) & 1) * 16);
    const uint32_t bFragOff = (uint32_t)((wn * 32 + (lane & 7) + ((lane >> 1) & 8)) * GPITCH_B
                                         + ((lane & 8) ? 16 : 0));

    for (int s = 0; s < GSTAGES; ++s) {
        CP_WAIT2();                   // stage s arrived (s+1, s+2 may be pending)
        __syncthreads();              // everyone past compute(s-1): buf (s+3)%4 is free

        if (s + 3 < GSTAGES) issue_stage(s + 3);
        CP_COMMIT();

        const uint32_t sbase = smBase + (uint32_t)(s & (NSTAGE - 1)) * GSTGB;
        const uint32_t aHB = sbase + aFragOff;
        const uint32_t aLB = sbase + MBUFB + aFragOff;
        const uint32_t bHB = sbase + 2 * MBUFB + bFragOff;
        const uint32_t bLB = sbase + 3 * MBUFB + bFragOff;

        uint32_t ah[4][4];
        #pragma unroll
        for (int mi = 0; mi < 4; ++mi)
            LDSM_X4(ah[mi][0], ah[mi][1], ah[mi][2], ah[mi][3], aHB + mi * 16 * GPITCH_B);
        uint32_t bh[4][2];
        LDSM_X4(bh[0][0], bh[0][1], bh[1][0], bh[1][1], bHB);
        LDSM_X4(bh[2][0], bh[2][1], bh[3][0], bh[3][1], bHB + 16 * GPITCH_B);
        uint32_t bl[4][2];
        LDSM_X4(bl[0][0], bl[0][1], bl[1][0], bl[1][1], bLB);
        LDSM_X4(bl[2][0], bl[2][1], bl[3][0], bl[3][1], bLB + 16 * GPITCH_B);

        #pragma unroll
        for (int mi = 0; mi < 4; ++mi)
            #pragma unroll
            for (int j = 0; j < 4; ++j)
                MMA_BF16(acc[mi][j], ah[mi], bh[j]);   // Ah*Bh
        #pragma unroll
        for (int mi = 0; mi < 4; ++mi)
            #pragma unroll
            for (int j = 0; j < 4; ++j)
                MMA_BF16(acc[mi][j], ah[mi], bl[j]);   // Ah*Bl

        uint32_t al[4][4];
        #pragma unroll
        for (int mi = 0; mi < 4; ++mi)
            LDSM_X4(al[mi][0], al[mi][1], al[mi][2], al[mi][3], aLB + mi * 16 * GPITCH_B);
        #pragma unroll
        for (int mi = 0; mi < 4; ++mi)
            #pragma unroll
            for (int j = 0; j < 4; ++j)
                MMA_BF16(acc[mi][j], al[mi], bh[j]);   // Al*Bh
    }

    // ---- epilogue ----
    const int g = lane >> 2, t = lane & 3;
    float2 bv[4];
    #pragma unroll
    for (int j = 0; j < 4; ++j) {
        const int col = n0 + wn * 32 + j * 8 + t * 2;
        bv[j].x = __ldg(bias + col);
        bv[j].y = __ldg(bias + col + 1);
    }
    #pragma unroll
    for (int mi = 0; mi < 4; ++mi) {
        const int row0 = m0 + wm * 64 + mi * 16 + g;
        #pragma unroll
        for (int j = 0; j < 4; ++j) {
            const int col = n0 + wn * 32 + j * 8 + t * 2;
            float2 o0 = { acc[mi][j][0] + bv[j].x, acc[mi][j][1] + bv[j].y };
            float2 o1 = { acc[mi][j][2] + bv[j].x, acc[mi][j][3] + bv[j].y };
            *reinterpret_cast<float2*>(C + (size_t)row0 * HIDN + col) = o0;
            *reinterpret_cast<float2*>(C + (size_t)(row0 + 8) * HIDN + col) = o1;
        }
    }
}

// ================= query-block sparse attention, register-tiled (unchanged R10) =================
#define KT_STRIDE 68
#define SC_STRIDE 67

__global__ __launch_bounds__(128) void attn_blk_kernel(
    const float* __restrict__ Q, const float* __restrict__ K,
    const float* __restrict__ V,
    __nv_bfloat16* __restrict__ Oh, __nv_bfloat16* __restrict__ Ol)
{
    extern __shared__ float sm[];
    float* Kt   = sm;                              // [131][68]
    float* Sc   = sm + 131 * KT_STRIDE;            // [64][67]
    float* Sinv = Sc + 64 * SC_STRIDE;             // [64]

    const int qb = blockIdx.x, h = blockIdx.y, b = blockIdx.z;
    const int i0 = qb * 64;
    const int jlo = (i0 > 64) ? (i0 - 64) : 0;
    const int nrows = i0 + 63 - jlo + 1;
    const bool extraG = (jlo > 0);
    const int grow = extraG ? 130 : 0;
    const int tid = threadIdx.x;
    const size_t base = (size_t)b * SQ * HIDN + (size_t)h * HDIM;

    for (int idx = tid; idx < nrows * 16; idx += 128) {
        int r = idx >> 4, c = idx & 15;
        float4 v = *reinterpret_cast<const float4*>(K + base + (size_t)(jlo + r) * HIDN + c * 4);
        *reinterpret_cast<float4*>(Kt + r * KT_STRIDE + c * 4) = v;
    }
    if (extraG && tid < 16) {
        float4 v = *reinterpret_cast<const float4*>(K + base + tid * 4);
        *reinterpret_cast<float4*>(Kt + 130 * KT_STRIDE + tid * 4) = v;
    }

    const int qg = tid >> 3;
    const int part = tid & 7;
    const int d0 = part * 8;
    const int iq0 = i0 + qg * 4;

    int r0q[4], nwq[4];
    #pragma unroll
    for (int qq = 0; qq < 4; ++qq) {
        const int iq = iq0 + qq;
        const int wloq = (iq > 64) ? (iq - 64) : 0;
        r0q[qq] = wloq - jlo;
        nwq[qq] = iq - wloq + 1;
    }

    float qr[4][8];
    #pragma unroll
    for (int qq = 0; qq < 4; ++qq) {
        const float* qp = Q + base + (size_t)(iq0 + qq) * HIDN + d0;
        float4 a = *reinterpret_cast<const float4*>(qp);
        float4 c = *reinterpret_cast<const float4*>(qp + 4);
        qr[qq][0] = a.x; qr[qq][1] = a.y; qr[qq][2] = a.z; qr[qq][3] = a.w;
        qr[qq][4] = c.x; qr[qq][5] = c.y; qr[qq][6] = c.z; qr[qq][7] = c.w;
    }
    __syncthreads();

    const int wq = tid >> 5;
    const int iFirst = i0 + wq * 16;
    const int iLast = iFirst + 15;
    const int rbeg = ((iFirst > 64) ? (iFirst - 64) : 0) - jlo;
    const int rend = iLast - jlo + 1;

    for (int row = rbeg; row < rend; ++row) {
        const float* kp = Kt + row * KT_STRIDE + d0;
        float4 k0 = *reinterpret_cast<const float4*>(kp);
        float4 k1 = *reinterpret_cast<const float4*>(kp + 4);
        #pragma unroll
        for (int qq = 0; qq < 4; ++qq) {
            float dot = qr[qq][0] * k0.x;
            dot = fmaf(qr[qq][1], k0.y, dot); dot = fmaf(qr[qq][2], k0.z, dot);
            dot = fmaf(qr[qq][3], k0.w, dot); dot = fmaf(qr[qq][4], k1.x, dot);
            dot = fmaf(qr[qq][5], k1.y, dot); dot = fmaf(qr[qq][6], k1.z, dot);
            dot = fmaf(qr[qq][7], k1.w, dot);
            dot += __shfl_xor_sync(0xffffffffu, dot, 1);
            dot += __shfl_xor_sync(0xffffffffu, dot, 2);
            dot += __shfl_xor_sync(0xffffffffu, dot, 4);
            const int s = row - r0q[qq];
            if (part == 0 && s >= 0 && s < nwq[qq])
                Sc[(qg * 4 + qq) * SC_STRIDE + s] = dot * 0.125f;
        }
    }
    {
        const float* kp = Kt + grow * KT_STRIDE + d0;
        float4 k0 = *reinterpret_cast<const float4*>(kp);
        float4 k1 = *reinterpret_cast<const float4*>(kp + 4);
        #pragma unroll
        for (int qq = 0; qq < 4; ++qq) {
            float dot = qr[qq][0] * k0.x;
            dot = fmaf(qr[qq][1], k0.y, dot); dot = fmaf(qr[qq][2], k0.z, dot);
            dot = fmaf(qr[qq][3], k0.w, dot); dot = fmaf(qr[qq][4], k1.x, dot);
            dot = fmaf(qr[qq][5], k1.y, dot); dot = fmaf(qr[qq][6], k1.z, dot);
            dot = fmaf(qr[qq][7], k1.w, dot);
            dot += __shfl_xor_sync(0xffffffffu, dot, 1);
            dot += __shfl_xor_sync(0xffffffffu, dot, 2);
            dot += __shfl_xor_sync(0xffffffffu, dot, 4);
            if (part == 0 && (iq0 + qq) > 64)
                Sc[(qg * 4 + qq) * SC_STRIDE + nwq[qq]] = dot * 0.125f;
        }
    }
    __syncthreads();

    for (int idx = tid; idx < nrows * 16; idx += 128) {
        int r = idx >> 4, c = idx & 15;
        float4 v = *reinterpret_cast<const float4*>(V + base + (size_t)(jlo + r) * HIDN + c * 4);
        *reinterpret_cast<float4*>(Kt + r * KT_STRIDE + c * 4) = v;
    }
    if (extraG && tid < 16) {
        float4 v = *reinterpret_cast<const float4*>(V + base + tid * 4);
        *reinterpret_cast<float4*>(Kt + 130 * KT_STRIDE + tid * 4) = v;
    }

    if (tid < 64) {
        const int iq = i0 + tid;
        const int wloq = (iq > 64) ? (iq - 64) : 0;
        const int nsq = (iq - wloq + 1) + ((wloq > 0) ? 1 : 0);
        float* sc = Sc + tid * SC_STRIDE;
        float m = -1e30f;
        for (int s = 0; s < nsq; ++s) m = fmaxf(m, sc[s]);
        float sum = 0.f;
        for (int s = 0; s < nsq; ++s) { float e = __expf(sc[s] - m); sc[s] = e; sum += e; }
        Sinv[tid] = 1.f / sum;
    }
    __syncthreads();

    float acc[4][8];
    #pragma unroll
    for (int qq = 0; qq < 4; ++qq)
        #pragma unroll
        for (int d = 0; d < 8; ++d) acc[qq][d] = 0.f;

    for (int row = rbeg; row < rend; ++row) {
        const float* vp = Kt + row * KT_STRIDE + d0;
        float4 v0 = *reinterpret_cast<const float4*>(vp);
        float4 v1 = *reinterpret_cast<const float4*>(vp + 4);
        #pragma unroll
        for (int qq = 0; qq < 4; ++qq) {
            const int s = row - r0q[qq];
            const bool ok = (s >= 0 && s < nwq[qq]);
            const int sc = ok ? s : 0;
            float pr = ok ? Sc[(qg * 4 + qq) * SC_STRIDE + sc] : 0.f;
            acc[qq][0] = fmaf(pr, v0.x, acc[qq][0]); acc[qq][1] = fmaf(pr, v0.y, acc[qq][1]);
            acc[qq][2] = fmaf(pr, v0.z, acc[qq][2]); acc[qq][3] = fmaf(pr, v0.w, acc[qq][3]);
            acc[qq][4] = fmaf(pr, v1.x, acc[qq][4]); acc[qq][5] = fmaf(pr, v1.y, acc[qq][5]);
            acc[qq][6] = fmaf(pr, v1.z, acc[qq][6]); acc[qq][7] = fmaf(pr, v1.w, acc[qq][7]);
        }
    }
    {
        const float* vp = Kt + grow * KT_STRIDE + d0;
        float4 v0 = *reinterpret_cast<const float4*>(vp);
        float4 v1 = *reinterpret_cast<const float4*>(vp + 4);
        #pragma unroll
        for (int qq = 0; qq < 4; ++qq) {
            float pr = ((iq0 + qq) > 64) ? Sc[(qg * 4 + qq) * SC_STRIDE + nwq[qq]] : 0.f;
            acc[qq][0] = fmaf(pr, v0.x, acc[qq][0]); acc[qq][1] = fmaf(pr, v0.y, acc[qq][1]);
            acc[qq][2] = fmaf(pr, v0.z, acc[qq][2]); acc[qq][3] = fmaf(pr, v0.w, acc[qq][3]);
            acc[qq][4] = fmaf(pr, v1.x, acc[qq][4]); acc[qq][5] = fmaf(pr, v1.y, acc[qq][5]);
            acc[qq][6] = fmaf(pr, v1.z, acc[qq][6]); acc[qq][7] = fmaf(pr, v1.w, acc[qq][7]);
        }
    }

    #pragma unroll
    for (int qq = 0; qq < 4; ++qq) {
        const float si = Sinv[qg * 4 + qq];
        uint32_t hw[4], lw[4];
        #pragma unroll
        for (int d = 0; d < 8; d += 2) {
            float v0 = acc[qq][d] * si, v1 = acc[qq][d + 1] * si;
            __nv_bfloat16 h0 = __float2bfloat16(v0), h1 = __float2bfloat16(v1);
            __nv_bfloat16 l0 = __float2bfloat16(v0 - __bfloat162float(h0));
            __nv_bfloat16 l1 = __float2bfloat16(v1 - __bfloat162float(h1));
            __nv_bfloat162 hp = __halves2bfloat162(h0, h1);
            __nv_bfloat162 lp = __halves2bfloat162(l0, l1);
            hw[d >> 1] = *reinterpret_cast<uint32_t*>(&hp);
            lw[d >> 1] = *reinterpret_cast<uint32_t*>(&lp);
        }
        const size_t ooff = base + (size_t)(iq0 + qq) * HIDN + d0;
        *reinterpret_cast<uint4*>(Oh + ooff) = make_uint4(hw[0], hw[1], hw[2], hw[3]);
        *reinterpret_cast<uint4*>(Ol + ooff) = make_uint4(lw[0], lw[1], lw[2], lw[3]);
    }
}

// ================= launch =================
extern "C" void kernel_launch(void* const* d_in, const int* in_sizes, int n_in,
                              void* d_out, int out_size)
{
    const float* X  = (const float*)d_in[0];
    const float* Wq = (const float*)d_in[1];
    const float* bq = (const float*)d_in[2];
    const float* Wk = (const float*)d_in[3];
    const float* bk = (const float*)d_in[4];
    const float* Wv = (const float*)d_in[5];
    const float* bv = (const float*)d_in[6];
    const float* Wo = (const float*)d_in[7];
    const float* bo = (const float*)d_in[8];
    float* out = (float*)d_out;

    float *Q, *K, *V;
    __nv_bfloat16 *Xh, *Xl, *Oh, *Ol, *Wh, *Wl;
    cudaGetSymbolAddress((void**)&Q, g_Q);
    cudaGetSymbolAddress((void**)&K, g_K);
    cudaGetSymbolAddress((void**)&V, g_V);
    cudaGetSymbolAddress((void**)&Xh, g_Xh);
    cudaGetSymbolAddress((void**)&Xl, g_Xl);
    cudaGetSymbolAddress((void**)&Oh, g_Oh);
    cudaGetSymbolAddress((void**)&Ol, g_Ol);
    cudaGetSymbolAddress((void**)&Wh, g_Wh);
    cudaGetSymbolAddress((void**)&Wl, g_Wl);

    const int attn_smem = (131 * KT_STRIDE + 64 * SC_STRIDE + 64) * (int)sizeof(float);
    cudaFuncSetAttribute(attn_blk_kernel, cudaFuncAttributeMaxDynamicSharedMemorySize, attn_smem);
    cudaFuncSetAttribute(gemm_mma_kernel, cudaFuncAttributeMaxDynamicSharedMemorySize, GEMM_SMEM);

    const int nX4 = MROWS * HIDN / 4;
    const int nW4 = HIDN * HIDN / 4;
    split_kernel<<<nX4 / 256, 256>>>(X, Xh, Xl, nX4);
    split_w_kernel<<<dim3(nW4 / 256, 4), 256>>>(Wq, Wk, Wv, Wo, Wh, Wl);

    const dim3 qkvGrid(HIDN / 128, MROWS / 128, 3);   // (8, 32, 3)
    gemm_mma_kernel<<<qkvGrid, 256, GEMM_SMEM>>>(Xh, Xl, Wh, Wl, 0, bq, bk, bv, Q, K, V);

    const dim3 attnGrid(SQ / 64, NHD, BZ);            // (32, 16, 2)
    attn_blk_kernel<<<attnGrid, 128, attn_smem>>>(Q, K, V, Oh, Ol);

    const dim3 oGrid(HIDN / 128, MROWS / 128, 1);
    gemm_mma_kernel<<<oGrid, 256, GEMM_SMEM>>>(Oh, Ol, Wh, Wl, 3, bo, bo, bo, out, out, out);
}

// round 13
// speedup vs baseline: 1.0313x; 1.0313x over previous
#include <cuda_runtime.h>
#include <cuda_bf16.h>
#include <cstdint>
#include <math.h>

// ---------------- problem constants ----------------
#define BZ   2
#define SQ   2048
#define HIDN 1024
#define NHD  16
#define HDIM 64
#define MROWS (BZ * SQ)      // 4096
#define WIN  64              // LOCAL_WINDOW / 2

// ---------------- scratch (no allocations allowed) ----------------
__device__ float g_Q[MROWS * HIDN];
__device__ float g_K[MROWS * HIDN];
__device__ float g_V[MROWS * HIDN];
__device__ __nv_bfloat16 g_Xh[MROWS * HIDN];
__device__ __nv_bfloat16 g_Xl[MROWS * HIDN];
__device__ __nv_bfloat16 g_Oh[MROWS * HIDN];
__device__ __nv_bfloat16 g_Ol[MROWS * HIDN];
__device__ __nv_bfloat16 g_Wh[4][HIDN * HIDN];
__device__ __nv_bfloat16 g_Wl[4][HIDN * HIDN];

// ================= helpers =================
__device__ __forceinline__ uint32_t smem_u32(const void* p) {
    uint32_t a;
    asm("{ .reg .u64 t; cvta.to.shared.u64 t, %1; cvt.u32.u64 %0, t; }" : "=r"(a) : "l"(p));
    return a;
}
#define CP_ASYNC16(sm, gm) \
    asm volatile("cp.async.cg.shared.global [%0], [%1], 16;" :: "r"(sm), "l"(gm) : "memory")
#define CP_COMMIT() asm volatile("cp.async.commit_group;" ::: "memory")
#define CP_WAIT1()  asm volatile("cp.async.wait_group 1;" ::: "memory")
#define CP_WAIT0()  asm volatile("cp.async.wait_group 0;" ::: "memory")

#define LDSM_X4(r0, r1, r2, r3, addr) \
    asm volatile("ldmatrix.sync.aligned.m8n8.x4.shared.b16 {%0,%1,%2,%3}, [%4];" \
        : "=r"(r0), "=r"(r1), "=r"(r2), "=r"(r3) : "r"(addr))

#define MMA_BF16(d, a, b) \
    asm volatile("mma.sync.aligned.m16n8k16.row.col.f32.bf16.bf16.f32 " \
        "{%0,%1,%2,%3}, {%4,%5,%6,%7}, {%8,%9}, {%0,%1,%2,%3};" \
        : "+f"((d)[0]), "+f"((d)[1]), "+f"((d)[2]), "+f"((d)[3]) \
        : "r"((a)[0]), "r"((a)[1]), "r"((a)[2]), "r"((a)[3]), "r"((b)[0]), "r"((b)[1]))

// ================= fp32 -> (bf16 hi, bf16 lo) split =================
__device__ __forceinline__ void split4(const float* __restrict__ src,
                                       __nv_bfloat16* __restrict__ hi,
                                       __nv_bfloat16* __restrict__ lo, int i) {
    float4 v = reinterpret_cast<const float4*>(src)[i];
    __nv_bfloat16 h0 = __float2bfloat16(v.x), h1 = __float2bfloat16(v.y);
    __nv_bfloat16 h2 = __float2bfloat16(v.z), h3 = __float2bfloat16(v.w);
    __nv_bfloat16 l0 = __float2bfloat16(v.x - __bfloat162float(h0));
    __nv_bfloat16 l1 = __float2bfloat16(v.y - __bfloat162float(h1));
    __nv_bfloat16 l2 = __float2bfloat16(v.z - __bfloat162float(h2));
    __nv_bfloat16 l3 = __float2bfloat16(v.w - __bfloat162float(h3));
    __nv_bfloat162 hA = __halves2bfloat162(h0, h1), hB = __halves2bfloat162(h2, h3);
    __nv_bfloat162 lA = __halves2bfloat162(l0, l1), lB = __halves2bfloat162(l2, l3);
    uint2 ho, lout;
    ho.x = *reinterpret_cast<uint32_t*>(&hA); ho.y = *reinterpret_cast<uint32_t*>(&hB);
    lout.x = *reinterpret_cast<uint32_t*>(&lA); lout.y = *reinterpret_cast<uint32_t*>(&lB);
    reinterpret_cast<uint2*>(hi)[i] = ho;
    reinterpret_cast<uint2*>(lo)[i] = lout;
}

__global__ __launch_bounds__(256) void split_kernel(const float* __restrict__ src,
                                                    __nv_bfloat16* __restrict__ hi,
                                                    __nv_bfloat16* __restrict__ lo, int n4) {
    int i = blockIdx.x * 256 + threadIdx.x;
    if (i < n4) split4(src, hi, lo, i);
}

__global__ __launch_bounds__(256) void split_w_kernel(
    const float* __restrict__ w0, const float* __restrict__ w1,
    const float* __restrict__ w2, const float* __restrict__ w3,
    __nv_bfloat16* __restrict__ hiBase, __nv_bfloat16* __restrict__ loBase)
{
    const int which = blockIdx.y;
    const float* src = (which == 0) ? w0 : (which == 1) ? w1 : (which == 2) ? w2 : w3;
    __nv_bfloat16* hi = hiBase + (size_t)which * HIDN * HIDN;
    __nv_bfloat16* lo = loBase + (size_t)which * HIDN * HIDN;
    int i = blockIdx.x * 256 + threadIdx.x;
    if (i < HIDN * HIDN / 4) split4(src, hi, lo, i);
}

// ================= mma.sync bf16x3 GEMM, fused-term stages (R10, proven 418us) =================
#define GPITCH_B 80u          // bytes per smem row
#define MBUFB    10240u       // one matrix per stage: 128 * 80
#define GSTGB    40960u       // 4 matrices per stage
#define GSTAGES  32           // 1024 / 32
#define GEMM_SMEM (2 * GSTGB) // 81920 (2-stage ring)

__global__ __launch_bounds__(256, 2) void gemm_mma_kernel(
    const __nv_bfloat16* __restrict__ Ah, const __nv_bfloat16* __restrict__ Al,
    const __nv_bfloat16* __restrict__ Whb, const __nv_bfloat16* __restrict__ Wlb,
    int wbase,
    const float* __restrict__ b0, const float* __restrict__ b1, const float* __restrict__ b2,
    float* __restrict__ C0, float* __restrict__ C1, float* __restrict__ C2)
{
    extern __shared__ __align__(16) char gsm[];

    const int z = blockIdx.z;
    const __nv_bfloat16* Bh = Whb + (size_t)(wbase + z) * HIDN * HIDN;
    const __nv_bfloat16* Bl = Wlb + (size_t)(wbase + z) * HIDN * HIDN;
    const float* bias = (z == 0) ? b0 : (z == 1) ? b1 : b2;
    float* C = (z == 0) ? C0 : (z == 1) ? C1 : C2;

    const int tid = threadIdx.x;
    const int wid = tid >> 5;
    const int lane = tid & 31;
    const int wm = wid & 1;          // warp row 0..1 (64 rows each)
    const int wn = wid >> 1;         // warp col 0..3 (32 cols each)
    const int m0 = blockIdx.y * 128;
    const int n0 = blockIdx.x * 128;

    const uint32_t smBase = smem_u32(gsm);

    const int lrow = tid >> 2;       // 0..63
    const int lchk = tid & 3;

    float acc[4][4][4];
    #pragma unroll
    for (int mi = 0; mi < 4; ++mi)
        #pragma unroll
        for (int j = 0; j < 4; ++j)
            #pragma unroll
            for (int r = 0; r < 4; ++r) acc[mi][j][r] = 0.f;

    auto issue_stage = [&](int s) {
        const int kk = s << 5;
        const uint32_t sbase = smBase + (uint32_t)(s & 1) * GSTGB;
        #pragma unroll
        for (int u = 0; u < 2; ++u) {
            const int r = u * 64 + lrow;
            const uint32_t so = (uint32_t)r * GPITCH_B + (uint32_t)lchk * 16u;
            const size_t ga = (size_t)(m0 + r) * HIDN + kk + lchk * 8;
            const size_t gb = (size_t)(n0 + r) * HIDN + kk + lchk * 8;
            CP_ASYNC16(sbase + so,              Ah + ga);
            CP_ASYNC16(sbase + MBUFB + so,      Al + ga);
            CP_ASYNC16(sbase + 2 * MBUFB + so,  Bh + gb);
            CP_ASYNC16(sbase + 3 * MBUFB + so,  Bl + gb);
        }
    };

    issue_stage(0); CP_COMMIT();
    issue_stage(1); CP_COMMIT();

    const uint32_t aFragOff = (uint32_t)((wm * 64 + (lane & 15)) * GPITCH_B + ((lane >> 4) & 1) * 16);
    const uint32_t bFragOff = (uint32_t)((wn * 32 + (lane & 7) + ((lane >> 1) & 8)) * GPITCH_B
                                         + ((lane & 8) ? 16 : 0));

    for (int s = 0; s < GSTAGES; ++s) {
        if (s + 1 < GSTAGES) CP_WAIT1(); else CP_WAIT0();
        __syncthreads();

        const uint32_t sbase = smBase + (uint32_t)(s & 1) * GSTGB;
        const uint32_t aHB = sbase + aFragOff;
        const uint32_t aLB = sbase + MBUFB + aFragOff;
        const uint32_t bHB = sbase + 2 * MBUFB + bFragOff;
        const uint32_t bLB = sbase + 3 * MBUFB + bFragOff;

        #pragma unroll
        for (int ks = 0; ks < 2; ++ks) {
            uint32_t ah[4][4];
            #pragma unroll
            for (int mi = 0; mi < 4; ++mi)
                LDSM_X4(ah[mi][0], ah[mi][1], ah[mi][2], ah[mi][3],
                        aHB + mi * 16 * GPITCH_B + ks * 32);
            uint32_t bh[4][2];
            LDSM_X4(bh[0][0], bh[0][1], bh[1][0], bh[1][1], bHB + ks * 32);
            LDSM_X4(bh[2][0], bh[2][1], bh[3][0], bh[3][1], bHB + 16 * GPITCH_B + ks * 32);
            uint32_t bl[4][2];
            LDSM_X4(bl[0][0], bl[0][1], bl[1][0], bl[1][1], bLB + ks * 32);
            LDSM_X4(bl[2][0], bl[2][1], bl[3][0], bl[3][1], bLB + 16 * GPITCH_B + ks * 32);

            #pragma unroll
            for (int mi = 0; mi < 4; ++mi)
                #pragma unroll
                for (int j = 0; j < 4; ++j)
                    MMA_BF16(acc[mi][j], ah[mi], bh[j]);   // Ah*Bh
            #pragma unroll
            for (int mi = 0; mi < 4; ++mi)
                #pragma unroll
                for (int j = 0; j < 4; ++j)
                    MMA_BF16(acc[mi][j], ah[mi], bl[j]);   // Ah*Bl

            uint32_t al[4][4];
            #pragma unroll
            for (int mi = 0; mi < 4; ++mi)
                LDSM_X4(al[mi][0], al[mi][1], al[mi][2], al[mi][3],
                        aLB + mi * 16 * GPITCH_B + ks * 32);
            #pragma unroll
            for (int mi = 0; mi < 4; ++mi)
                #pragma unroll
                for (int j = 0; j < 4; ++j)
                    MMA_BF16(acc[mi][j], al[mi], bh[j]);   // Al*Bh
        }
        __syncthreads();
        if (s + 2 < GSTAGES) { issue_stage(s + 2); CP_COMMIT(); }
    }

    // ---- epilogue ----
    const int g = lane >> 2, t = lane & 3;
    float2 bv[4];
    #pragma unroll
    for (int j = 0; j < 4; ++j) {
        const int col = n0 + wn * 32 + j * 8 + t * 2;
        bv[j].x = __ldg(bias + col);
        bv[j].y = __ldg(bias + col + 1);
    }
    #pragma unroll
    for (int mi = 0; mi < 4; ++mi) {
        const int row0 = m0 + wm * 64 + mi * 16 + g;
        #pragma unroll
        for (int j = 0; j < 4; ++j) {
            const int col = n0 + wn * 32 + j * 8 + t * 2;
            float2 o0 = { acc[mi][j][0] + bv[j].x, acc[mi][j][1] + bv[j].y };
            float2 o1 = { acc[mi][j][2] + bv[j].x, acc[mi][j][3] + bv[j].y };
            *reinterpret_cast<float2*>(C + (size_t)row0 * HIDN + col) = o0;
            *reinterpret_cast<float2*>(C + (size_t)(row0 + 8) * HIDN + col) = o1;
        }
    }
}

// ================= sparse attention: 32-query CTAs for occupancy =================
// 128 threads = 16 q-groups x 8 dim-parts; 2 queries x 8 dims per thread.
// KT_STRIDE must be a multiple of 4 (float4 accesses) -> 68.
#define KT_STRIDE 68
#define SC_STRIDE 67
#define QBLK 32
#define GROW 96   // tile row holding key j=0 when jlo>0

__global__ __launch_bounds__(128) void attn_blk_kernel(
    const float* __restrict__ Q, const float* __restrict__ K,
    const float* __restrict__ V,
    __nv_bfloat16* __restrict__ Oh, __nv_bfloat16* __restrict__ Ol)
{
    extern __shared__ float sm[];
    float* Kt   = sm;                              // [97][68]
    float* Sc   = sm + 97 * KT_STRIDE;             // [32][67]
    float* Sinv = Sc + QBLK * SC_STRIDE;           // [32]

    const int qb = blockIdx.x, h = blockIdx.y, b = blockIdx.z;
    const int i0 = qb * QBLK;
    const int jlo = (i0 > 64) ? (i0 - 64) : 0;
    const int nrows = i0 + QBLK - 1 - jlo + 1;     // <= 96
    const bool extraG = (jlo > 0);
    const int grow = extraG ? GROW : 0;
    const int tid = threadIdx.x;
    const size_t base = (size_t)b * SQ * HIDN + (size_t)h * HDIM;

    // ---- load K tile ----
    for (int idx = tid; idx < nrows * 16; idx += 128) {
        int r = idx >> 4, c = idx & 15;
        float4 v = *reinterpret_cast<const float4*>(K + base + (size_t)(jlo + r) * HIDN + c * 4);
        *reinterpret_cast<float4*>(Kt + r * KT_STRIDE + c * 4) = v;
    }
    if (extraG && tid < 16) {
        float4 v = *reinterpret_cast<const float4*>(K + base + tid * 4);
        *reinterpret_cast<float4*>(Kt + GROW * KT_STRIDE + tid * 4) = v;
    }

    const int qg = tid >> 3;          // 0..15 (2 queries each)
    const int part = tid & 7;         // 0..7  (8 dims each)
    const int d0 = part * 8;
    const int iq0 = i0 + qg * 2;

    int r0q[2], nwq[2];
    #pragma unroll
    for (int qq = 0; qq < 2; ++qq) {
        const int iq = iq0 + qq;
        const int wloq = (iq > 64) ? (iq - 64) : 0;
        r0q[qq] = wloq - jlo;
        nwq[qq] = iq - wloq + 1;
    }

    float qr[2][8];
    #pragma unroll
    for (int qq = 0; qq < 2; ++qq) {
        const float* qp = Q + base + (size_t)(iq0 + qq) * HIDN + d0;
        float4 a = *reinterpret_cast<const float4*>(qp);
        float4 c = *reinterpret_cast<const float4*>(qp + 4);
        qr[qq][0] = a.x; qr[qq][1] = a.y; qr[qq][2] = a.z; qr[qq][3] = a.w;
        qr[qq][4] = c.x; qr[qq][5] = c.y; qr[qq][6] = c.z; qr[qq][7] = c.w;
    }
    __syncthreads();

    // warp-uniform row bounds (warp covers 8 consecutive queries)
    const int wq = tid >> 5;
    const int iFirst = i0 + wq * 8;
    const int iLast = iFirst + 7;
    const int rbeg = ((iFirst > 64) ? (iFirst - 64) : 0) - jlo;
    const int rend = iLast - jlo + 1;

    // ---- scores ----
    for (int row = rbeg; row < rend; ++row) {
        const float* kp = Kt + row * KT_STRIDE + d0;
        float4 k0 = *reinterpret_cast<const float4*>(kp);
        float4 k1 = *reinterpret_cast<const float4*>(kp + 4);
        #pragma unroll
        for (int qq = 0; qq < 2; ++qq) {
            float dot = qr[qq][0] * k0.x;
            dot = fmaf(qr[qq][1], k0.y, dot); dot = fmaf(qr[qq][2], k0.z, dot);
            dot = fmaf(qr[qq][3], k0.w, dot); dot = fmaf(qr[qq][4], k1.x, dot);
            dot = fmaf(qr[qq][5], k1.y, dot); dot = fmaf(qr[qq][6], k1.z, dot);
            dot = fmaf(qr[qq][7], k1.w, dot);
            dot += __shfl_xor_sync(0xffffffffu, dot, 1);
            dot += __shfl_xor_sync(0xffffffffu, dot, 2);
            dot += __shfl_xor_sync(0xffffffffu, dot, 4);
            const int s = row - r0q[qq];
            if (part == 0 && s >= 0 && s < nwq[qq])
                Sc[(qg * 2 + qq) * SC_STRIDE + s] = dot * 0.125f;
        }
    }
    // global key j=0 (uniform extra iteration)
    {
        const float* kp = Kt + grow * KT_STRIDE + d0;
        float4 k0 = *reinterpret_cast<const float4*>(kp);
        float4 k1 = *reinterpret_cast<const float4*>(kp + 4);
        #pragma unroll
        for (int qq = 0; qq < 2; ++qq) {
            float dot = qr[qq][0] * k0.x;
            dot = fmaf(qr[qq][1], k0.y, dot); dot = fmaf(qr[qq][2], k0.z, dot);
            dot = fmaf(qr[qq][3], k0.w, dot); dot = fmaf(qr[qq][4], k1.x, dot);
            dot = fmaf(qr[qq][5], k1.y, dot); dot = fmaf(qr[qq][6], k1.z, dot);
            dot = fmaf(qr[qq][7], k1.w, dot);
            dot += __shfl_xor_sync(0xffffffffu, dot, 1);
            dot += __shfl_xor_sync(0xffffffffu, dot, 2);
            dot += __shfl_xor_sync(0xffffffffu, dot, 4);
            if (part == 0 && (iq0 + qq) > 64)
                Sc[(qg * 2 + qq) * SC_STRIDE + nwq[qq]] = dot * 0.125f;
        }
    }
    __syncthreads();

    // ---- load V tile (overwrites Kt) ----
    for (int idx = tid; idx < nrows * 16; idx += 128) {
        int r = idx >> 4, c = idx & 15;
        float4 v = *reinterpret_cast<const float4*>(V + base + (size_t)(jlo + r) * HIDN + c * 4);
        *reinterpret_cast<float4*>(Kt + r * KT_STRIDE + c * 4) = v;
    }
    if (extraG && tid < 16) {
        float4 v = *reinterpret_cast<const float4*>(V + base + tid * 4);
        *reinterpret_cast<float4*>(Kt + GROW * KT_STRIDE + tid * 4) = v;
    }

    // ---- softmax (one thread per query) ----
    if (tid < QBLK) {
        const int iq = i0 + tid;
        const int wloq = (iq > 64) ? (iq - 64) : 0;
        const int nsq = (iq - wloq + 1) + ((wloq > 0) ? 1 : 0);
        float* sc = Sc + tid * SC_STRIDE;
        float m = -1e30f;
        for (int s = 0; s < nsq; ++s) m = fmaxf(m, sc[s]);
        float sum = 0.f;
        for (int s = 0; s < nsq; ++s) { float e = __expf(sc[s] - m); sc[s] = e; sum += e; }
        Sinv[tid] = 1.f / sum;
    }
    __syncthreads();

    // ---- output ----
    float acc[2][8];
    #pragma unroll
    for (int qq = 0; qq < 2; ++qq)
        #pragma unroll
        for (int d = 0; d < 8; ++d) acc[qq][d] = 0.f;

    for (int row = rbeg; row < rend; ++row) {
        const float* vp = Kt + row * KT_STRIDE + d0;
        float4 v0 = *reinterpret_cast<const float4*>(vp);
        float4 v1 = *reinterpret_cast<const float4*>(vp + 4);
        #pragma unroll
        for (int qq = 0; qq < 2; ++qq) {
            const int s = row - r0q[qq];
            const bool ok = (s >= 0 && s < nwq[qq]);
            float pr = ok ? Sc[(qg * 2 + qq) * SC_STRIDE + (ok ? s : 0)] : 0.f;
            acc[qq][0] = fmaf(pr, v0.x, acc[qq][0]); acc[qq][1] = fmaf(pr, v0.y, acc[qq][1]);
            acc[qq][2] = fmaf(pr, v0.z, acc[qq][2]); acc[qq][3] = fmaf(pr, v0.w, acc[qq][3]);
            acc[qq][4] = fmaf(pr, v1.x, acc[qq][4]); acc[qq][5] = fmaf(pr, v1.y, acc[qq][5]);
            acc[qq][6] = fmaf(pr, v1.z, acc[qq][6]); acc[qq][7] = fmaf(pr, v1.w, acc[qq][7]);
        }
    }
    {
        const float* vp = Kt + grow * KT_STRIDE + d0;
        float4 v0 = *reinterpret_cast<const float4*>(vp);
        float4 v1 = *reinterpret_cast<const float4*>(vp + 4);
        #pragma unroll
        for (int qq = 0; qq < 2; ++qq) {
            float pr = ((iq0 + qq) > 64) ? Sc[(qg * 2 + qq) * SC_STRIDE + nwq[qq]] : 0.f;
            acc[qq][0] = fmaf(pr, v0.x, acc[qq][0]); acc[qq][1] = fmaf(pr, v0.y, acc[qq][1]);
            acc[qq][2] = fmaf(pr, v0.z, acc[qq][2]); acc[qq][3] = fmaf(pr, v0.w, acc[qq][3]);
            acc[qq][4] = fmaf(pr, v1.x, acc[qq][4]); acc[qq][5] = fmaf(pr, v1.y, acc[qq][5]);
            acc[qq][6] = fmaf(pr, v1.z, acc[qq][6]); acc[qq][7] = fmaf(pr, v1.w, acc[qq][7]);
        }
    }

    // ---- write Oh/Ol (fused bf16 hi/lo split) ----
    #pragma unroll
    for (int qq = 0; qq < 2; ++qq) {
        const float si = Sinv[qg * 2 + qq];
        uint32_t hw[4], lw[4];
        #pragma unroll
        for (int d = 0; d < 8; d += 2) {
            float v0 = acc[qq][d] * si, v1 = acc[qq][d + 1] * si;
            __nv_bfloat16 h0 = __float2bfloat16(v0), h1 = __float2bfloat16(v1);
            __nv_bfloat16 l0 = __float2bfloat16(v0 - __bfloat162float(h0));
            __nv_bfloat16 l1 = __float2bfloat16(v1 - __bfloat162float(h1));
            __nv_bfloat162 hp = __halves2bfloat162(h0, h1);
            __nv_bfloat162 lp = __halves2bfloat162(l0, l1);
            hw[d >> 1] = *reinterpret_cast<uint32_t*>(&hp);
            lw[d >> 1] = *reinterpret_cast<uint32_t*>(&lp);
        }
        const size_t ooff = base + (size_t)(iq0 + qq) * HIDN + d0;
        *reinterpret_cast<uint4*>(Oh + ooff) = make_uint4(hw[0], hw[1], hw[2], hw[3]);
        *reinterpret_cast<uint4*>(Ol + ooff) = make_uint4(lw[0], lw[1], lw[2], lw[3]);
    }
}

// ================= launch =================
extern "C" void kernel_launch(void* const* d_in, const int* in_sizes, int n_in,
                              void* d_out, int out_size)
{
    const float* X  = (const float*)d_in[0];
    const float* Wq = (const float*)d_in[1];
    const float* bq = (const float*)d_in[2];
    const float* Wk = (const float*)d_in[3];
    const float* bk = (const float*)d_in[4];
    const float* Wv = (const float*)d_in[5];
    const float* bv = (const float*)d_in[6];
    const float* Wo = (const float*)d_in[7];
    const float* bo = (const float*)d_in[8];
    float* out = (float*)d_out;

    float *Q, *K, *V;
    __nv_bfloat16 *Xh, *Xl, *Oh, *Ol, *Wh, *Wl;
    cudaGetSymbolAddress((void**)&Q, g_Q);
    cudaGetSymbolAddress((void**)&K, g_K);
    cudaGetSymbolAddress((void**)&V, g_V);
    cudaGetSymbolAddress((void**)&Xh, g_Xh);
    cudaGetSymbolAddress((void**)&Xl, g_Xl);
    cudaGetSymbolAddress((void**)&Oh, g_Oh);
    cudaGetSymbolAddress((void**)&Ol, g_Ol);
    cudaGetSymbolAddress((void**)&Wh, g_Wh);
    cudaGetSymbolAddress((void**)&Wl, g_Wl);

    const int attn_smem = (97 * KT_STRIDE + QBLK * SC_STRIDE + QBLK) * (int)sizeof(float);
    cudaFuncSetAttribute(attn_blk_kernel, cudaFuncAttributeMaxDynamicSharedMemorySize, attn_smem);
    cudaFuncSetAttribute(gemm_mma_kernel, cudaFuncAttributeMaxDynamicSharedMemorySize, GEMM_SMEM);

    const int nX4 = MROWS * HIDN / 4;
    const int nW4 = HIDN * HIDN / 4;
    split_kernel<<<nX4 / 256, 256>>>(X, Xh, Xl, nX4);
    split_w_kernel<<<dim3(nW4 / 256, 4), 256>>>(Wq, Wk, Wv, Wo, Wh, Wl);

    const dim3 qkvGrid(HIDN / 128, MROWS / 128, 3);   // (8, 32, 3)
    gemm_mma_kernel<<<qkvGrid, 256, GEMM_SMEM>>>(Xh, Xl, Wh, Wl, 0, bq, bk, bv, Q, K, V);

    const dim3 attnGrid(SQ / QBLK, NHD, BZ);          // (64, 16, 2) = 2048 CTAs
    attn_blk_kernel<<<attnGrid, 128, attn_smem>>>(Q, K, V, Oh, Ol);

    const dim3 oGrid(HIDN / 128, MROWS / 128, 1);
    gemm_mma_kernel<<<oGrid, 256, GEMM_SMEM>>>(Oh, Ol, Wh, Wl, 3, bo, bo, bo, out, out, out);
}

// round 14
// speedup vs baseline: 1.0372x; 1.0057x over previous
#include <cuda_runtime.h>
#include <cuda_bf16.h>
#include <cstdint>
#include <math.h>

// ---------------- problem constants ----------------
#define BZ   2
#define SQ   2048
#define HIDN 1024
#define NHD  16
#define HDIM 64
#define MROWS (BZ * SQ)      // 4096
#define WIN  64              // LOCAL_WINDOW / 2

// ---------------- scratch (no allocations allowed) ----------------
__device__ float g_Q[MROWS * HIDN];
__device__ float g_K[MROWS * HIDN];
__device__ float g_V[MROWS * HIDN];
__device__ __nv_bfloat16 g_Xh[MROWS * HIDN];
__device__ __nv_bfloat16 g_Xl[MROWS * HIDN];
__device__ __nv_bfloat16 g_Oh[MROWS * HIDN];
__device__ __nv_bfloat16 g_Ol[MROWS * HIDN];
__device__ __nv_bfloat16 g_Wh[4][HIDN * HIDN];
__device__ __nv_bfloat16 g_Wl[4][HIDN * HIDN];

// ================= helpers =================
__device__ __forceinline__ uint32_t smem_u32(const void* p) {
    uint32_t a;
    asm("{ .reg .u64 t; cvta.to.shared.u64 t, %1; cvt.u32.u64 %0, t; }" : "=r"(a) : "l"(p));
    return a;
}
#define CP_ASYNC16(sm, gm) \
    asm volatile("cp.async.cg.shared.global [%0], [%1], 16;" :: "r"(sm), "l"(gm) : "memory")
#define CP_COMMIT() asm volatile("cp.async.commit_group;" ::: "memory")
#define CP_WAIT1()  asm volatile("cp.async.wait_group 1;" ::: "memory")
#define CP_WAIT0()  asm volatile("cp.async.wait_group 0;" ::: "memory")

#define LDSM_X4(r0, r1, r2, r3, addr) \
    asm volatile("ldmatrix.sync.aligned.m8n8.x4.shared.b16 {%0,%1,%2,%3}, [%4];" \
        : "=r"(r0), "=r"(r1), "=r"(r2), "=r"(r3) : "r"(addr))

#define MMA_BF16(d, a, b) \
    asm volatile("mma.sync.aligned.m16n8k16.row.col.f32.bf16.bf16.f32 " \
        "{%0,%1,%2,%3}, {%4,%5,%6,%7}, {%8,%9}, {%0,%1,%2,%3};" \
        : "+f"((d)[0]), "+f"((d)[1]), "+f"((d)[2]), "+f"((d)[3]) \
        : "r"((a)[0]), "r"((a)[1]), "r"((a)[2]), "r"((a)[3]), "r"((b)[0]), "r"((b)[1]))

// ================= fp32 -> (bf16 hi, bf16 lo) split =================
__device__ __forceinline__ void split4(const float* __restrict__ src,
                                       __nv_bfloat16* __restrict__ hi,
                                       __nv_bfloat16* __restrict__ lo, int i) {
    float4 v = reinterpret_cast<const float4*>(src)[i];
    __nv_bfloat16 h0 = __float2bfloat16(v.x), h1 = __float2bfloat16(v.y);
    __nv_bfloat16 h2 = __float2bfloat16(v.z), h3 = __float2bfloat16(v.w);
    __nv_bfloat16 l0 = __float2bfloat16(v.x - __bfloat162float(h0));
    __nv_bfloat16 l1 = __float2bfloat16(v.y - __bfloat162float(h1));
    __nv_bfloat16 l2 = __float2bfloat16(v.z - __bfloat162float(h2));
    __nv_bfloat16 l3 = __float2bfloat16(v.w - __bfloat162float(h3));
    __nv_bfloat162 hA = __halves2bfloat162(h0, h1), hB = __halves2bfloat162(h2, h3);
    __nv_bfloat162 lA = __halves2bfloat162(l0, l1), lB = __halves2bfloat162(l2, l3);
    uint2 ho, lout;
    ho.x = *reinterpret_cast<uint32_t*>(&hA); ho.y = *reinterpret_cast<uint32_t*>(&hB);
    lout.x = *reinterpret_cast<uint32_t*>(&lA); lout.y = *reinterpret_cast<uint32_t*>(&lB);
    reinterpret_cast<uint2*>(hi)[i] = ho;
    reinterpret_cast<uint2*>(lo)[i] = lout;
}

__global__ __launch_bounds__(256) void split_kernel(const float* __restrict__ src,
                                                    __nv_bfloat16* __restrict__ hi,
                                                    __nv_bfloat16* __restrict__ lo, int n4) {
    int i = blockIdx.x * 256 + threadIdx.x;
    if (i < n4) split4(src, hi, lo, i);
}

__global__ __launch_bounds__(256) void split_w_kernel(
    const float* __restrict__ w0, const float* __restrict__ w1,
    const float* __restrict__ w2, const float* __restrict__ w3,
    __nv_bfloat16* __restrict__ hiBase, __nv_bfloat16* __restrict__ loBase)
{
    const int which = blockIdx.y;
    const float* src = (which == 0) ? w0 : (which == 1) ? w1 : (which == 2) ? w2 : w3;
    __nv_bfloat16* hi = hiBase + (size_t)which * HIDN * HIDN;
    __nv_bfloat16* lo = loBase + (size_t)which * HIDN * HIDN;
    int i = blockIdx.x * 256 + threadIdx.x;
    if (i < HIDN * HIDN / 4) split4(src, hi, lo, i);
}

// ================= mma.sync bf16x3 GEMM: fused terms + 32-warp shape =================
// 128x128 CTA tile, 512 threads = 16 warps (4 row x 4 col), warp tile 32x32.
// Fused 3-term per BK=32 stage (Ah*Bh + Ah*Bl + Al*Bh), fragments sequenced to
// keep live regs under the 64-reg cap of __launch_bounds__(512,2) -> 32 warps/SM.
#define GPITCH_B 80u          // bytes per smem row
#define MBUFB    10240u       // one matrix per stage: 128 * 80
#define GSTGB    40960u       // 4 matrices per stage
#define GSTAGES  32           // 1024 / 32
#define GEMM_SMEM (2 * GSTGB) // 81920 (2-stage ring)

__global__ __launch_bounds__(512, 2) void gemm_mma_kernel(
    const __nv_bfloat16* __restrict__ Ah, const __nv_bfloat16* __restrict__ Al,
    const __nv_bfloat16* __restrict__ Whb, const __nv_bfloat16* __restrict__ Wlb,
    int wbase,
    const float* __restrict__ b0, const float* __restrict__ b1, const float* __restrict__ b2,
    float* __restrict__ C0, float* __restrict__ C1, float* __restrict__ C2)
{
    extern __shared__ __align__(16) char gsm[];

    const int z = blockIdx.z;
    const __nv_bfloat16* Bh = Whb + (size_t)(wbase + z) * HIDN * HIDN;
    const __nv_bfloat16* Bl = Wlb + (size_t)(wbase + z) * HIDN * HIDN;
    const float* bias = (z == 0) ? b0 : (z == 1) ? b1 : b2;
    float* C = (z == 0) ? C0 : (z == 1) ? C1 : C2;

    const int tid = threadIdx.x;
    const int wid = tid >> 5;
    const int lane = tid & 31;
    const int wm = wid & 3;          // warp row 0..3 (32 rows each)
    const int wn = wid >> 2;         // warp col 0..3 (32 cols each)
    const int m0 = blockIdx.y * 128;
    const int n0 = blockIdx.x * 128;

    const uint32_t smBase = smem_u32(gsm);

    const int lrow = tid >> 2;       // 0..127
    const int lchk = tid & 3;

    float acc[2][4][4];              // [mi 16-rows][j 8-cols][frag] = 32 regs
    #pragma unroll
    for (int mi = 0; mi < 2; ++mi)
        #pragma unroll
        for (int j = 0; j < 4; ++j)
            #pragma unroll
            for (int r = 0; r < 4; ++r) acc[mi][j][r] = 0.f;

    auto issue_stage = [&](int s) {
        const int kk = s << 5;
        const uint32_t sbase = smBase + (uint32_t)(s & 1) * GSTGB;
        const uint32_t so = (uint32_t)lrow * GPITCH_B + (uint32_t)lchk * 16u;
        const size_t ga = (size_t)(m0 + lrow) * HIDN + kk + lchk * 8;
        const size_t gb = (size_t)(n0 + lrow) * HIDN + kk + lchk * 8;
        CP_ASYNC16(sbase + so,              Ah + ga);
        CP_ASYNC16(sbase + MBUFB + so,      Al + ga);
        CP_ASYNC16(sbase + 2 * MBUFB + so,  Bh + gb);
        CP_ASYNC16(sbase + 3 * MBUFB + so,  Bl + gb);
    };

    issue_stage(0); CP_COMMIT();
    issue_stage(1); CP_COMMIT();

    const uint32_t aFragOff = (uint32_t)((wm * 32 + (lane & 15)) * GPITCH_B + ((lane >> 4) & 1) * 16);
    const uint32_t bFragOff = (uint32_t)((wn * 32 + (lane & 7) + ((lane >> 1) & 8)) * GPITCH_B
                                         + ((lane & 8) ? 16 : 0));

    for (int s = 0; s < GSTAGES; ++s) {
        if (s + 1 < GSTAGES) CP_WAIT1(); else CP_WAIT0();
        __syncthreads();

        const uint32_t sbase = smBase + (uint32_t)(s & 1) * GSTGB;
        const uint32_t aHB = sbase + aFragOff;
        const uint32_t aLB = sbase + MBUFB + aFragOff;
        const uint32_t bHB = sbase + 2 * MBUFB + bFragOff;
        const uint32_t bLB = sbase + 3 * MBUFB + bFragOff;

        #pragma unroll
        for (int ks = 0; ks < 2; ++ks) {
            // Sequenced to limit live registers: ah+bh -> MMA, +bl -> MMA (bh
            // stays), ah dies, al loads into its place -> MMA with bh.
            uint32_t ah[2][4];
            LDSM_X4(ah[0][0], ah[0][1], ah[0][2], ah[0][3], aHB + ks * 32);
            LDSM_X4(ah[1][0], ah[1][1], ah[1][2], ah[1][3], aHB + 16 * GPITCH_B + ks * 32);
            uint32_t bh[4][2];
            LDSM_X4(bh[0][0], bh[0][1], bh[1][0], bh[1][1], bHB + ks * 32);
            LDSM_X4(bh[2][0], bh[2][1], bh[3][0], bh[3][1], bHB + 16 * GPITCH_B + ks * 32);
            #pragma unroll
            for (int mi = 0; mi < 2; ++mi)
                #pragma unroll
                for (int j = 0; j < 4; ++j)
                    MMA_BF16(acc[mi][j], ah[mi], bh[j]);   // Ah*Bh

            uint32_t bl[4][2];
            LDSM_X4(bl[0][0], bl[0][1], bl[1][0], bl[1][1], bLB + ks * 32);
            LDSM_X4(bl[2][0], bl[2][1], bl[3][0], bl[3][1], bLB + 16 * GPITCH_B + ks * 32);
            #pragma unroll
            for (int mi = 0; mi < 2; ++mi)
                #pragma unroll
                for (int j = 0; j < 4; ++j)
                    MMA_BF16(acc[mi][j], ah[mi], bl[j]);   // Ah*Bl

            uint32_t al[2][4];
            LDSM_X4(al[0][0], al[0][1], al[0][2], al[0][3], aLB + ks * 32);
            LDSM_X4(al[1][0], al[1][1], al[1][2], al[1][3], aLB + 16 * GPITCH_B + ks * 32);
            #pragma unroll
            for (int mi = 0; mi < 2; ++mi)
                #pragma unroll
                for (int j = 0; j < 4; ++j)
                    MMA_BF16(acc[mi][j], al[mi], bh[j]);   // Al*Bh
        }
        __syncthreads();
        if (s + 2 < GSTAGES) { issue_stage(s + 2); CP_COMMIT(); }
    }

    // ---- epilogue ----
    const int g = lane >> 2, t = lane & 3;
    float2 bv[4];
    #pragma unroll
    for (int j = 0; j < 4; ++j) {
        const int col = n0 + wn * 32 + j * 8 + t * 2;
        bv[j].x = __ldg(bias + col);
        bv[j].y = __ldg(bias + col + 1);
    }
    #pragma unroll
    for (int mi = 0; mi < 2; ++mi) {
        const int row0 = m0 + wm * 32 + mi * 16 + g;
        #pragma unroll
        for (int j = 0; j < 4; ++j) {
            const int col = n0 + wn * 32 + j * 8 + t * 2;
            float2 o0 = { acc[mi][j][0] + bv[j].x, acc[mi][j][1] + bv[j].y };
            float2 o1 = { acc[mi][j][2] + bv[j].x, acc[mi][j][3] + bv[j].y };
            *reinterpret_cast<float2*>(C + (size_t)row0 * HIDN + col) = o0;
            *reinterpret_cast<float2*>(C + (size_t)(row0 + 8) * HIDN + col) = o1;
        }
    }
}

// ================= query-block sparse attention, register-tiled (R10 exact) =================
#define KT_STRIDE 68
#define SC_STRIDE 67

__global__ __launch_bounds__(128) void attn_blk_kernel(
    const float* __restrict__ Q, const float* __restrict__ K,
    const float* __restrict__ V,
    __nv_bfloat16* __restrict__ Oh, __nv_bfloat16* __restrict__ Ol)
{
    extern __shared__ float sm[];
    float* Kt   = sm;                              // [131][68]
    float* Sc   = sm + 131 * KT_STRIDE;            // [64][67]
    float* Sinv = Sc + 64 * SC_STRIDE;             // [64]

    const int qb = blockIdx.x, h = blockIdx.y, b = blockIdx.z;
    const int i0 = qb * 64;
    const int jlo = (i0 > 64) ? (i0 - 64) : 0;
    const int nrows = i0 + 63 - jlo + 1;
    const bool extraG = (jlo > 0);
    const int grow = extraG ? 130 : 0;
    const int tid = threadIdx.x;
    const size_t base = (size_t)b * SQ * HIDN + (size_t)h * HDIM;

    for (int idx = tid; idx < nrows * 16; idx += 128) {
        int r = idx >> 4, c = idx & 15;
        float4 v = *reinterpret_cast<const float4*>(K + base + (size_t)(jlo + r) * HIDN + c * 4);
        *reinterpret_cast<float4*>(Kt + r * KT_STRIDE + c * 4) = v;
    }
    if (extraG && tid < 16) {
        float4 v = *reinterpret_cast<const float4*>(K + base + tid * 4);
        *reinterpret_cast<float4*>(Kt + 130 * KT_STRIDE + tid * 4) = v;
    }

    const int qg = tid >> 3;
    const int part = tid & 7;
    const int d0 = part * 8;
    const int iq0 = i0 + qg * 4;

    int r0q[4], nwq[4];
    #pragma unroll
    for (int qq = 0; qq < 4; ++qq) {
        const int iq = iq0 + qq;
        const int wloq = (iq > 64) ? (iq - 64) : 0;
        r0q[qq] = wloq - jlo;
        nwq[qq] = iq - wloq + 1;
    }

    float qr[4][8];
    #pragma unroll
    for (int qq = 0; qq < 4; ++qq) {
        const float* qp = Q + base + (size_t)(iq0 + qq) * HIDN + d0;
        float4 a = *reinterpret_cast<const float4*>(qp);
        float4 c = *reinterpret_cast<const float4*>(qp + 4);
        qr[qq][0] = a.x; qr[qq][1] = a.y; qr[qq][2] = a.z; qr[qq][3] = a.w;
        qr[qq][4] = c.x; qr[qq][5] = c.y; qr[qq][6] = c.z; qr[qq][7] = c.w;
    }
    __syncthreads();

    const int wq = tid >> 5;
    const int iFirst = i0 + wq * 16;
    const int iLast = iFirst + 15;
    const int rbeg = ((iFirst > 64) ? (iFirst - 64) : 0) - jlo;
    const int rend = iLast - jlo + 1;

    for (int row = rbeg; row < rend; ++row) {
        const float* kp = Kt + row * KT_STRIDE + d0;
        float4 k0 = *reinterpret_cast<const float4*>(kp);
        float4 k1 = *reinterpret_cast<const float4*>(kp + 4);
        #pragma unroll
        for (int qq = 0; qq < 4; ++qq) {
            float dot = qr[qq][0] * k0.x;
            dot = fmaf(qr[qq][1], k0.y, dot); dot = fmaf(qr[qq][2], k0.z, dot);
            dot = fmaf(qr[qq][3], k0.w, dot); dot = fmaf(qr[qq][4], k1.x, dot);
            dot = fmaf(qr[qq][5], k1.y, dot); dot = fmaf(qr[qq][6], k1.z, dot);
            dot = fmaf(qr[qq][7], k1.w, dot);
            dot += __shfl_xor_sync(0xffffffffu, dot, 1);
            dot += __shfl_xor_sync(0xffffffffu, dot, 2);
            dot += __shfl_xor_sync(0xffffffffu, dot, 4);
            const int s = row - r0q[qq];
            if (part == 0 && s >= 0 && s < nwq[qq])
                Sc[(qg * 4 + qq) * SC_STRIDE + s] = dot * 0.125f;
        }
    }
    {
        const float* kp = Kt + grow * KT_STRIDE + d0;
        float4 k0 = *reinterpret_cast<const float4*>(kp);
        float4 k1 = *reinterpret_cast<const float4*>(kp + 4);
        #pragma unroll
        for (int qq = 0; qq < 4; ++qq) {
            float dot = qr[qq][0] * k0.x;
            dot = fmaf(qr[qq][1], k0.y, dot); dot = fmaf(qr[qq][2], k0.z, dot);
            dot = fmaf(qr[qq][3], k0.w, dot); dot = fmaf(qr[qq][4], k1.x, dot);
            dot = fmaf(qr[qq][5], k1.y, dot); dot = fmaf(qr[qq][6], k1.z, dot);
            dot = fmaf(qr[qq][7], k1.w, dot);
            dot += __shfl_xor_sync(0xffffffffu, dot, 1);
            dot += __shfl_xor_sync(0xffffffffu, dot, 2);
            dot += __shfl_xor_sync(0xffffffffu, dot, 4);
            if (part == 0 && (iq0 + qq) > 64)
                Sc[(qg * 4 + qq) * SC_STRIDE + nwq[qq]] = dot * 0.125f;
        }
    }
    __syncthreads();

    for (int idx = tid; idx < nrows * 16; idx += 128) {
        int r = idx >> 4, c = idx & 15;
        float4 v = *reinterpret_cast<const float4*>(V + base + (size_t)(jlo + r) * HIDN + c * 4);
        *reinterpret_cast<float4*>(Kt + r * KT_STRIDE + c * 4) = v;
    }
    if (extraG && tid < 16) {
        float4 v = *reinterpret_cast<const float4*>(V + base + tid * 4);
        *reinterpret_cast<float4*>(Kt + 130 * KT_STRIDE + tid * 4) = v;
    }

    if (tid < 64) {
        const int iq = i0 + tid;
        const int wloq = (iq > 64) ? (iq - 64) : 0;
        const int nsq = (iq - wloq + 1) + ((wloq > 0) ? 1 : 0);
        float* sc = Sc + tid * SC_STRIDE;
        float m = -1e30f;
        for (int s = 0; s < nsq; ++s) m = fmaxf(m, sc[s]);
        float sum = 0.f;
        for (int s = 0; s < nsq; ++s) { float e = __expf(sc[s] - m); sc[s] = e; sum += e; }
        Sinv[tid] = 1.f / sum;
    }
    __syncthreads();

    float acc[4][8];
    #pragma unroll
    for (int qq = 0; qq < 4; ++qq)
        #pragma unroll
        for (int d = 0; d < 8; ++d) acc[qq][d] = 0.f;

    for (int row = rbeg; row < rend; ++row) {
        const float* vp = Kt + row * KT_STRIDE + d0;
        float4 v0 = *reinterpret_cast<const float4*>(vp);
        float4 v1 = *reinterpret_cast<const float4*>(vp + 4);
        #pragma unroll
        for (int qq = 0; qq < 4; ++qq) {
            const int s = row - r0q[qq];
            const bool ok = (s >= 0 && s < nwq[qq]);
            float pr = ok ? Sc[(qg * 4 + qq) * SC_STRIDE + (ok ? s : 0)] : 0.f;
            acc[qq][0] = fmaf(pr, v0.x, acc[qq][0]); acc[qq][1] = fmaf(pr, v0.y, acc[qq][1]);
            acc[qq][2] = fmaf(pr, v0.z, acc[qq][2]); acc[qq][3] = fmaf(pr, v0.w, acc[qq][3]);
            acc[qq][4] = fmaf(pr, v1.x, acc[qq][4]); acc[qq][5] = fmaf(pr, v1.y, acc[qq][5]);
            acc[qq][6] = fmaf(pr, v1.z, acc[qq][6]); acc[qq][7] = fmaf(pr, v1.w, acc[qq][7]);
        }
    }
    {
        const float* vp = Kt + grow * KT_STRIDE + d0;
        float4 v0 = *reinterpret_cast<const float4*>(vp);
        float4 v1 = *reinterpret_cast<const float4*>(vp + 4);
        #pragma unroll
        for (int qq = 0; qq < 4; ++qq) {
            float pr = ((iq0 + qq) > 64) ? Sc[(qg * 4 + qq) * SC_STRIDE + nwq[qq]] : 0.f;
            acc[qq][0] = fmaf(pr, v0.x, acc[qq][0]); acc[qq][1] = fmaf(pr, v0.y, acc[qq][1]);
            acc[qq][2] = fmaf(pr, v0.z, acc[qq][2]); acc[qq][3] = fmaf(pr, v0.w, acc[qq][3]);
            acc[qq][4] = fmaf(pr, v1.x, acc[qq][4]); acc[qq][5] = fmaf(pr, v1.y, acc[qq][5]);
            acc[qq][6] = fmaf(pr, v1.z, acc[qq][6]); acc[qq][7] = fmaf(pr, v1.w, acc[qq][7]);
        }
    }

    #pragma unroll
    for (int qq = 0; qq < 4; ++qq) {
        const float si = Sinv[qg * 4 + qq];
        uint32_t hw[4], lw[4];
        #pragma unroll
        for (int d = 0; d < 8; d += 2) {
            float v0 = acc[qq][d] * si, v1 = acc[qq][d + 1] * si;
            __nv_bfloat16 h0 = __float2bfloat16(v0), h1 = __float2bfloat16(v1);
            __nv_bfloat16 l0 = __float2bfloat16(v0 - __bfloat162float(h0));
            __nv_bfloat16 l1 = __float2bfloat16(v1 - __bfloat162float(h1));
            __nv_bfloat162 hp = __halves2bfloat162(h0, h1);
            __nv_bfloat162 lp = __halves2bfloat162(l0, l1);
            hw[d >> 1] = *reinterpret_cast<uint32_t*>(&hp);
            lw[d >> 1] = *reinterpret_cast<uint32_t*>(&lp);
        }
        const size_t ooff = base + (size_t)(iq0 + qq) * HIDN + d0;
        *reinterpret_cast<uint4*>(Oh + ooff) = make_uint4(hw[0], hw[1], hw[2], hw[3]);
        *reinterpret_cast<uint4*>(Ol + ooff) = make_uint4(lw[0], lw[1], lw[2], lw[3]);
    }
}

// ================= launch =================
extern "C" void kernel_launch(void* const* d_in, const int* in_sizes, int n_in,
                              void* d_out, int out_size)
{
    const float* X  = (const float*)d_in[0];
    const float* Wq = (const float*)d_in[1];
    const float* bq = (const float*)d_in[2];
    const float* Wk = (const float*)d_in[3];
    const float* bk = (const float*)d_in[4];
    const float* Wv = (const float*)d_in[5];
    const float* bv = (const float*)d_in[6];
    const float* Wo = (const float*)d_in[7];
    const float* bo = (const float*)d_in[8];
    float* out = (float*)d_out;

    float *Q, *K, *V;
    __nv_bfloat16 *Xh, *Xl, *Oh, *Ol, *Wh, *Wl;
    cudaGetSymbolAddress((void**)&Q, g_Q);
    cudaGetSymbolAddress((void**)&K, g_K);
    cudaGetSymbolAddress((void**)&V, g_V);
    cudaGetSymbolAddress((void**)&Xh, g_Xh);
    cudaGetSymbolAddress((void**)&Xl, g_Xl);
    cudaGetSymbolAddress((void**)&Oh, g_Oh);
    cudaGetSymbolAddress((void**)&Ol, g_Ol);
    cudaGetSymbolAddress((void**)&Wh, g_Wh);
    cudaGetSymbolAddress((void**)&Wl, g_Wl);

    const int attn_smem = (131 * KT_STRIDE + 64 * SC_STRIDE + 64) * (int)sizeof(float);
    cudaFuncSetAttribute(attn_blk_kernel, cudaFuncAttributeMaxDynamicSharedMemorySize, attn_smem);
    cudaFuncSetAttribute(gemm_mma_kernel, cudaFuncAttributeMaxDynamicSharedMemorySize, GEMM_SMEM);

    const int nX4 = MROWS * HIDN / 4;
    const int nW4 = HIDN * HIDN / 4;
    split_kernel<<<nX4 / 256, 256>>>(X, Xh, Xl, nX4);
    split_w_kernel<<<dim3(nW4 / 256, 4), 256>>>(Wq, Wk, Wv, Wo, Wh, Wl);

    const dim3 qkvGrid(HIDN / 128, MROWS / 128, 3);   // (8, 32, 3)
    gemm_mma_kernel<<<qkvGrid, 512, GEMM_SMEM>>>(Xh, Xl, Wh, Wl, 0, bq, bk, bv, Q, K, V);

    const dim3 attnGrid(SQ / 64, NHD, BZ);            // (32, 16, 2)
    attn_blk_kernel<<<attnGrid, 128, attn_smem>>>(Q, K, V, Oh, Ol);

    const dim3 oGrid(HIDN / 128, MROWS / 128, 1);
    gemm_mma_kernel<<<oGrid, 512, GEMM_SMEM>>>(Oh, Ol, Wh, Wl, 3, bo, bo, bo, out, out, out);
}

// round 15
// speedup vs baseline: 1.0732x; 1.0347x over previous
#include <cuda_runtime.h>
#include <cuda_bf16.h>
#include <cstdint>
#include <math.h>

// ---------------- problem constants ----------------
#define BZ   2
#define SQ   2048
#define HIDN 1024
#define NHD  16
#define HDIM 64
#define MROWS (BZ * SQ)      // 4096
#define WIN  64              // LOCAL_WINDOW / 2

// ---------------- scratch (no allocations allowed) ----------------
__device__ float g_Q[MROWS * HIDN];
__device__ float g_K[MROWS * HIDN];
__device__ float g_V[MROWS * HIDN];
__device__ __nv_bfloat16 g_Xh[MROWS * HIDN];
__device__ __nv_bfloat16 g_Xl[MROWS * HIDN];
__device__ __nv_bfloat16 g_Oh[MROWS * HIDN];
__device__ __nv_bfloat16 g_Ol[MROWS * HIDN];
__device__ __nv_bfloat16 g_Wh[4][HIDN * HIDN];
__device__ __nv_bfloat16 g_Wl[4][HIDN * HIDN];

// ================= helpers =================
__device__ __forceinline__ uint32_t smem_u32(const void* p) {
    uint32_t a;
    asm("{ .reg .u64 t; cvta.to.shared.u64 t, %1; cvt.u32.u64 %0, t; }" : "=r"(a) : "l"(p));
    return a;
}
#define CP_ASYNC16(sm, gm) \
    asm volatile("cp.async.cg.shared.global [%0], [%1], 16;" :: "r"(sm), "l"(gm) : "memory")
#define CP_COMMIT() asm volatile("cp.async.commit_group;" ::: "memory")
#define CP_WAIT1()  asm volatile("cp.async.wait_group 1;" ::: "memory")
#define CP_WAIT0()  asm volatile("cp.async.wait_group 0;" ::: "memory")

#define LDSM_X4(r0, r1, r2, r3, addr) \
    asm volatile("ldmatrix.sync.aligned.m8n8.x4.shared.b16 {%0,%1,%2,%3}, [%4];" \
        : "=r"(r0), "=r"(r1), "=r"(r2), "=r"(r3) : "r"(addr))

#define MMA_BF16(d, a, b) \
    asm volatile("mma.sync.aligned.m16n8k16.row.col.f32.bf16.bf16.f32 " \
        "{%0,%1,%2,%3}, {%4,%5,%6,%7}, {%8,%9}, {%0,%1,%2,%3};" \
        : "+f"((d)[0]), "+f"((d)[1]), "+f"((d)[2]), "+f"((d)[3]) \
        : "r"((a)[0]), "r"((a)[1]), "r"((a)[2]), "r"((a)[3]), "r"((b)[0]), "r"((b)[1]))

// ---- packed f32x2 (Blackwell base ISA) ----
#define PACK2(out, lo, hi) \
    asm("mov.b64 %0, {%1, %2};" : "=l"(out) : "r"(lo), "r"(hi))
#define UNPACK2(lo, hi, in) \
    asm("mov.b64 {%0, %1}, %2;" : "=r"(lo), "=r"(hi) : "l"(in))
#define FMA2(d, a, b) \
    asm("fma.rn.f32x2 %0, %1, %2, %0;" : "+l"(d) : "l"(a), "l"(b))

__device__ __forceinline__ uint64_t pack_f4_lo(const float4& v) {
    uint64_t r; PACK2(r, __float_as_uint(v.x), __float_as_uint(v.y)); return r;
}
__device__ __forceinline__ uint64_t pack_f4_hi(const float4& v) {
    uint64_t r; PACK2(r, __float_as_uint(v.z), __float_as_uint(v.w)); return r;
}

// ================= fp32 -> (bf16 hi, bf16 lo) split =================
__device__ __forceinline__ void split4(const float* __restrict__ src,
                                       __nv_bfloat16* __restrict__ hi,
                                       __nv_bfloat16* __restrict__ lo, int i) {
    float4 v = reinterpret_cast<const float4*>(src)[i];
    __nv_bfloat16 h0 = __float2bfloat16(v.x), h1 = __float2bfloat16(v.y);
    __nv_bfloat16 h2 = __float2bfloat16(v.z), h3 = __float2bfloat16(v.w);
    __nv_bfloat16 l0 = __float2bfloat16(v.x - __bfloat162float(h0));
    __nv_bfloat16 l1 = __float2bfloat16(v.y - __bfloat162float(h1));
    __nv_bfloat16 l2 = __float2bfloat16(v.z - __bfloat162float(h2));
    __nv_bfloat16 l3 = __float2bfloat16(v.w - __bfloat162float(h3));
    __nv_bfloat162 hA = __halves2bfloat162(h0, h1), hB = __halves2bfloat162(h2, h3);
    __nv_bfloat162 lA = __halves2bfloat162(l0, l1), lB = __halves2bfloat162(l2, l3);
    uint2 ho, lout;
    ho.x = *reinterpret_cast<uint32_t*>(&hA); ho.y = *reinterpret_cast<uint32_t*>(&hB);
    lout.x = *reinterpret_cast<uint32_t*>(&lA); lout.y = *reinterpret_cast<uint32_t*>(&lB);
    reinterpret_cast<uint2*>(hi)[i] = ho;
    reinterpret_cast<uint2*>(lo)[i] = lout;
}

__global__ __launch_bounds__(256) void split_kernel(const float* __restrict__ src,
                                                    __nv_bfloat16* __restrict__ hi,
                                                    __nv_bfloat16* __restrict__ lo, int n4) {
    int i = blockIdx.x * 256 + threadIdx.x;
    if (i < n4) split4(src, hi, lo, i);
}

__global__ __launch_bounds__(256) void split_w_kernel(
    const float* __restrict__ w0, const float* __restrict__ w1,
    const float* __restrict__ w2, const float* __restrict__ w3,
    __nv_bfloat16* __restrict__ hiBase, __nv_bfloat16* __restrict__ loBase)
{
    const int which = blockIdx.y;
    const float* src = (which == 0) ? w0 : (which == 1) ? w1 : (which == 2) ? w2 : w3;
    __nv_bfloat16* hi = hiBase + (size_t)which * HIDN * HIDN;
    __nv_bfloat16* lo = loBase + (size_t)which * HIDN * HIDN;
    int i = blockIdx.x * 256 + threadIdx.x;
    if (i < HIDN * HIDN / 4) split4(src, hi, lo, i);
}

// ================= mma.sync bf16x3 GEMM, fused-term stages (R10 exact, proven 418us) =================
#define GPITCH_B 80u          // bytes per smem row
#define MBUFB    10240u       // one matrix per stage: 128 * 80
#define GSTGB    40960u       // 4 matrices per stage
#define GSTAGES  32           // 1024 / 32
#define GEMM_SMEM (2 * GSTGB) // 81920 (2-stage ring)

__global__ __launch_bounds__(256, 2) void gemm_mma_kernel(
    const __nv_bfloat16* __restrict__ Ah, const __nv_bfloat16* __restrict__ Al,
    const __nv_bfloat16* __restrict__ Whb, const __nv_bfloat16* __restrict__ Wlb,
    int wbase,
    const float* __restrict__ b0, const float* __restrict__ b1, const float* __restrict__ b2,
    float* __restrict__ C0, float* __restrict__ C1, float* __restrict__ C2)
{
    extern __shared__ __align__(16) char gsm[];

    const int z = blockIdx.z;
    const __nv_bfloat16* Bh = Whb + (size_t)(wbase + z) * HIDN * HIDN;
    const __nv_bfloat16* Bl = Wlb + (size_t)(wbase + z) * HIDN * HIDN;
    const float* bias = (z == 0) ? b0 : (z == 1) ? b1 : b2;
    float* C = (z == 0) ? C0 : (z == 1) ? C1 : C2;

    const int tid = threadIdx.x;
    const int wid = tid >> 5;
    const int lane = tid & 31;
    const int wm = wid & 1;          // warp row 0..1 (64 rows each)
    const int wn = wid >> 1;         // warp col 0..3 (32 cols each)
    const int m0 = blockIdx.y * 128;
    const int n0 = blockIdx.x * 128;

    const uint32_t smBase = smem_u32(gsm);

    const int lrow = tid >> 2;       // 0..63
    const int lchk = tid & 3;

    float acc[4][4][4];
    #pragma unroll
    for (int mi = 0; mi < 4; ++mi)
        #pragma unroll
        for (int j = 0; j < 4; ++j)
            #pragma unroll
            for (int r = 0; r < 4; ++r) acc[mi][j][r] = 0.f;

    auto issue_stage = [&](int s) {
        const int kk = s << 5;
        const uint32_t sbase = smBase + (uint32_t)(s & 1) * GSTGB;
        #pragma unroll
        for (int u = 0; u < 2; ++u) {
            const int r = u * 64 + lrow;
            const uint32_t so = (uint32_t)r * GPITCH_B + (uint32_t)lchk * 16u;
            const size_t ga = (size_t)(m0 + r) * HIDN + kk + lchk * 8;
            const size_t gb = (size_t)(n0 + r) * HIDN + kk + lchk * 8;
            CP_ASYNC16(sbase + so,              Ah + ga);
            CP_ASYNC16(sbase + MBUFB + so,      Al + ga);
            CP_ASYNC16(sbase + 2 * MBUFB + so,  Bh + gb);
            CP_ASYNC16(sbase + 3 * MBUFB + so,  Bl + gb);
        }
    };

    issue_stage(0); CP_COMMIT();
    issue_stage(1); CP_COMMIT();

    const uint32_t aFragOff = (uint32_t)((wm * 64 + (lane & 15)) * GPITCH_B + ((lane >> 4) & 1) * 16);
    const uint32_t bFragOff = (uint32_t)((wn * 32 + (lane & 7) + ((lane >> 1) & 8)) * GPITCH_B
                                         + ((lane & 8) ? 16 : 0));

    for (int s = 0; s < GSTAGES; ++s) {
        if (s + 1 < GSTAGES) CP_WAIT1(); else CP_WAIT0();
        __syncthreads();

        const uint32_t sbase = smBase + (uint32_t)(s & 1) * GSTGB;
        const uint32_t aHB = sbase + aFragOff;
        const uint32_t aLB = sbase + MBUFB + aFragOff;
        const uint32_t bHB = sbase + 2 * MBUFB + bFragOff;
        const uint32_t bLB = sbase + 3 * MBUFB + bFragOff;

        #pragma unroll
        for (int ks = 0; ks < 2; ++ks) {
            uint32_t ah[4][4];
            #pragma unroll
            for (int mi = 0; mi < 4; ++mi)
                LDSM_X4(ah[mi][0], ah[mi][1], ah[mi][2], ah[mi][3],
                        aHB + mi * 16 * GPITCH_B + ks * 32);
            uint32_t bh[4][2];
            LDSM_X4(bh[0][0], bh[0][1], bh[1][0], bh[1][1], bHB + ks * 32);
            LDSM_X4(bh[2][0], bh[2][1], bh[3][0], bh[3][1], bHB + 16 * GPITCH_B + ks * 32);
            uint32_t bl[4][2];
            LDSM_X4(bl[0][0], bl[0][1], bl[1][0], bl[1][1], bLB + ks * 32);
            LDSM_X4(bl[2][0], bl[2][1], bl[3][0], bl[3][1], bLB + 16 * GPITCH_B + ks * 32);

            #pragma unroll
            for (int mi = 0; mi < 4; ++mi)
                #pragma unroll
                for (int j = 0; j < 4; ++j)
                    MMA_BF16(acc[mi][j], ah[mi], bh[j]);   // Ah*Bh
            #pragma unroll
            for (int mi = 0; mi < 4; ++mi)
                #pragma unroll
                for (int j = 0; j < 4; ++j)
                    MMA_BF16(acc[mi][j], ah[mi], bl[j]);   // Ah*Bl

            uint32_t al[4][4];
            #pragma unroll
            for (int mi = 0; mi < 4; ++mi)
                LDSM_X4(al[mi][0], al[mi][1], al[mi][2], al[mi][3],
                        aLB + mi * 16 * GPITCH_B + ks * 32);
            #pragma unroll
            for (int mi = 0; mi < 4; ++mi)
                #pragma unroll
                for (int j = 0; j < 4; ++j)
                    MMA_BF16(acc[mi][j], al[mi], bh[j]);   // Al*Bh
        }
        __syncthreads();
        if (s + 2 < GSTAGES) { issue_stage(s + 2); CP_COMMIT(); }
    }

    // ---- epilogue ----
    const int g = lane >> 2, t = lane & 3;
    float2 bv[4];
    #pragma unroll
    for (int j = 0; j < 4; ++j) {
        const int col = n0 + wn * 32 + j * 8 + t * 2;
        bv[j].x = __ldg(bias + col);
        bv[j].y = __ldg(bias + col + 1);
    }
    #pragma unroll
    for (int mi = 0; mi < 4; ++mi) {
        const int row0 = m0 + wm * 64 + mi * 16 + g;
        #pragma unroll
        for (int j = 0; j < 4; ++j) {
            const int col = n0 + wn * 32 + j * 8 + t * 2;
            float2 o0 = { acc[mi][j][0] + bv[j].x, acc[mi][j][1] + bv[j].y };
            float2 o1 = { acc[mi][j][2] + bv[j].x, acc[mi][j][3] + bv[j].y };
            *reinterpret_cast<float2*>(C + (size_t)row0 * HIDN + col) = o0;
            *reinterpret_cast<float2*>(C + (size_t)(row0 + 8) * HIDN + col) = o1;
        }
    }
}

// ================= query-block sparse attention, register-tiled + f32x2 FMA =================
#define KT_STRIDE 68
#define SC_STRIDE 67

__global__ __launch_bounds__(128) void attn_blk_kernel(
    const float* __restrict__ Q, const float* __restrict__ K,
    const float* __restrict__ V,
    __nv_bfloat16* __restrict__ Oh, __nv_bfloat16* __restrict__ Ol)
{
    extern __shared__ float sm[];
    float* Kt   = sm;                              // [131][68]
    float* Sc   = sm + 131 * KT_STRIDE;            // [64][67]
    float* Sinv = Sc + 64 * SC_STRIDE;             // [64]

    const int qb = blockIdx.x, h = blockIdx.y, b = blockIdx.z;
    const int i0 = qb * 64;
    const int jlo = (i0 > 64) ? (i0 - 64) : 0;
    const int nrows = i0 + 63 - jlo + 1;
    const bool extraG = (jlo > 0);
    const int grow = extraG ? 130 : 0;
    const int tid = threadIdx.x;
    const size_t base = (size_t)b * SQ * HIDN + (size_t)h * HDIM;

    for (int idx = tid; idx < nrows * 16; idx += 128) {
        int r = idx >> 4, c = idx & 15;
        float4 v = *reinterpret_cast<const float4*>(K + base + (size_t)(jlo + r) * HIDN + c * 4);
        *reinterpret_cast<float4*>(Kt + r * KT_STRIDE + c * 4) = v;
    }
    if (extraG && tid < 16) {
        float4 v = *reinterpret_cast<const float4*>(K + base + tid * 4);
        *reinterpret_cast<float4*>(Kt + 130 * KT_STRIDE + tid * 4) = v;
    }

    const int qg = tid >> 3;
    const int part = tid & 7;
    const int d0 = part * 8;
    const int iq0 = i0 + qg * 4;

    int r0q[4], nwq[4];
    #pragma unroll
    for (int qq = 0; qq < 4; ++qq) {
        const int iq = iq0 + qq;
        const int wloq = (iq > 64) ? (iq - 64) : 0;
        r0q[qq] = wloq - jlo;
        nwq[qq] = iq - wloq + 1;
    }

    // Q registers packed as f32x2: 4 queries x 4 pairs
    uint64_t qp2[4][4];
    #pragma unroll
    for (int qq = 0; qq < 4; ++qq) {
        const float* qp = Q + base + (size_t)(iq0 + qq) * HIDN + d0;
        float4 a = *reinterpret_cast<const float4*>(qp);
        float4 c = *reinterpret_cast<const float4*>(qp + 4);
        qp2[qq][0] = pack_f4_lo(a); qp2[qq][1] = pack_f4_hi(a);
        qp2[qq][2] = pack_f4_lo(c); qp2[qq][3] = pack_f4_hi(c);
    }
    __syncthreads();

    const int wq = tid >> 5;
    const int iFirst = i0 + wq * 16;
    const int iLast = iFirst + 15;
    const int rbeg = ((iFirst > 64) ? (iFirst - 64) : 0) - jlo;
    const int rend = iLast - jlo + 1;

    // ---- scores (f32x2 dot products) ----
    for (int row = rbeg; row < rend; ++row) {
        const float* kp = Kt + row * KT_STRIDE + d0;
        float4 k0 = *reinterpret_cast<const float4*>(kp);
        float4 k1 = *reinterpret_cast<const float4*>(kp + 4);
        uint64_t kA = pack_f4_lo(k0), kB = pack_f4_hi(k0);
        uint64_t kC = pack_f4_lo(k1), kD = pack_f4_hi(k1);
        #pragma unroll
        for (int qq = 0; qq < 4; ++qq) {
            uint64_t d2 = 0;
            FMA2(d2, qp2[qq][0], kA); FMA2(d2, qp2[qq][1], kB);
            FMA2(d2, qp2[qq][2], kC); FMA2(d2, qp2[qq][3], kD);
            uint32_t lo, hi; UNPACK2(lo, hi, d2);
            float dot = __uint_as_float(lo) + __uint_as_float(hi);
            dot += __shfl_xor_sync(0xffffffffu, dot, 1);
            dot += __shfl_xor_sync(0xffffffffu, dot, 2);
            dot += __shfl_xor_sync(0xffffffffu, dot, 4);
            const int s = row - r0q[qq];
            if (part == 0 && s >= 0 && s < nwq[qq])
                Sc[(qg * 4 + qq) * SC_STRIDE + s] = dot * 0.125f;
        }
    }
    {
        const float* kp = Kt + grow * KT_STRIDE + d0;
        float4 k0 = *reinterpret_cast<const float4*>(kp);
        float4 k1 = *reinterpret_cast<const float4*>(kp + 4);
        uint64_t kA = pack_f4_lo(k0), kB = pack_f4_hi(k0);
        uint64_t kC = pack_f4_lo(k1), kD = pack_f4_hi(k1);
        #pragma unroll
        for (int qq = 0; qq < 4; ++qq) {
            uint64_t d2 = 0;
            FMA2(d2, qp2[qq][0], kA); FMA2(d2, qp2[qq][1], kB);
            FMA2(d2, qp2[qq][2], kC); FMA2(d2, qp2[qq][3], kD);
            uint32_t lo, hi; UNPACK2(lo, hi, d2);
            float dot = __uint_as_float(lo) + __uint_as_float(hi);
            dot += __shfl_xor_sync(0xffffffffu, dot, 1);
            dot += __shfl_xor_sync(0xffffffffu, dot, 2);
            dot += __shfl_xor_sync(0xffffffffu, dot, 4);
            if (part == 0 && (iq0 + qq) > 64)
                Sc[(qg * 4 + qq) * SC_STRIDE + nwq[qq]] = dot * 0.125f;
        }
    }
    __syncthreads();

    for (int idx = tid; idx < nrows * 16; idx += 128) {
        int r = idx >> 4, c = idx & 15;
        float4 v = *reinterpret_cast<const float4*>(V + base + (size_t)(jlo + r) * HIDN + c * 4);
        *reinterpret_cast<float4*>(Kt + r * KT_STRIDE + c * 4) = v;
    }
    if (extraG && tid < 16) {
        float4 v = *reinterpret_cast<const float4*>(V + base + tid * 4);
        *reinterpret_cast<float4*>(Kt + 130 * KT_STRIDE + tid * 4) = v;
    }

    if (tid < 64) {
        const int iq = i0 + tid;
        const int wloq = (iq > 64) ? (iq - 64) : 0;
        const int nsq = (iq - wloq + 1) + ((wloq > 0) ? 1 : 0);
        float* sc = Sc + tid * SC_STRIDE;
        float m = -1e30f;
        for (int s = 0; s < nsq; ++s) m = fmaxf(m, sc[s]);
        float sum = 0.f;
        for (int s = 0; s < nsq; ++s) { float e = __expf(sc[s] - m); sc[s] = e; sum += e; }
        Sinv[tid] = 1.f / sum;
    }
    __syncthreads();

    // ---- output (f32x2 accumulation) ----
    uint64_t acc2[4][4];
    #pragma unroll
    for (int qq = 0; qq < 4; ++qq)
        #pragma unroll
        for (int d = 0; d < 4; ++d) acc2[qq][d] = 0;

    for (int row = rbeg; row < rend; ++row) {
        const float* vp = Kt + row * KT_STRIDE + d0;
        float4 v0 = *reinterpret_cast<const float4*>(vp);
        float4 v1 = *reinterpret_cast<const float4*>(vp + 4);
        uint64_t vA = pack_f4_lo(v0), vB = pack_f4_hi(v0);
        uint64_t vC = pack_f4_lo(v1), vD = pack_f4_hi(v1);
        #pragma unroll
        for (int qq = 0; qq < 4; ++qq) {
            const int s = row - r0q[qq];
            const bool ok = (s >= 0 && s < nwq[qq]);
            float pr = ok ? Sc[(qg * 4 + qq) * SC_STRIDE + (ok ? s : 0)] : 0.f;
            uint64_t pr2; PACK2(pr2, __float_as_uint(pr), __float_as_uint(pr));
            FMA2(acc2[qq][0], pr2, vA); FMA2(acc2[qq][1], pr2, vB);
            FMA2(acc2[qq][2], pr2, vC); FMA2(acc2[qq][3], pr2, vD);
        }
    }
    {
        const float* vp = Kt + grow * KT_STRIDE + d0;
        float4 v0 = *reinterpret_cast<const float4*>(vp);
        float4 v1 = *reinterpret_cast<const float4*>(vp + 4);
        uint64_t vA = pack_f4_lo(v0), vB = pack_f4_hi(v0);
        uint64_t vC = pack_f4_lo(v1), vD = pack_f4_hi(v1);
        #pragma unroll
        for (int qq = 0; qq < 4; ++qq) {
            float pr = ((iq0 + qq) > 64) ? Sc[(qg * 4 + qq) * SC_STRIDE + nwq[qq]] : 0.f;
            uint64_t pr2; PACK2(pr2, __float_as_uint(pr), __float_as_uint(pr));
            FMA2(acc2[qq][0], pr2, vA); FMA2(acc2[qq][1], pr2, vB);
            FMA2(acc2[qq][2], pr2, vC); FMA2(acc2[qq][3], pr2, vD);
        }
    }

    #pragma unroll
    for (int qq = 0; qq < 4; ++qq) {
        const float si = Sinv[qg * 4 + qq];
        float accf[8];
        #pragma unroll
        for (int d = 0; d < 4; ++d) {
            uint32_t lo, hi; UNPACK2(lo, hi, acc2[qq][d]);
            accf[2 * d] = __uint_as_float(lo);
            accf[2 * d + 1] = __uint_as_float(hi);
        }
        uint32_t hw[4], lw[4];
        #pragma unroll
        for (int d = 0; d < 8; d += 2) {
            float v0 = accf[d] * si, v1 = accf[d + 1] * si;
            __nv_bfloat16 h0 = __float2bfloat16(v0), h1 = __float2bfloat16(v1);
            __nv_bfloat16 l0 = __float2bfloat16(v0 - __bfloat162float(h0));
            __nv_bfloat16 l1 = __float2bfloat16(v1 - __bfloat162float(h1));
            __nv_bfloat162 hp = __halves2bfloat162(h0, h1);
            __nv_bfloat162 lp = __halves2bfloat162(l0, l1);
            hw[d >> 1] = *reinterpret_cast<uint32_t*>(&hp);
            lw[d >> 1] = *reinterpret_cast<uint32_t*>(&lp);
        }
        const size_t ooff = base + (size_t)(iq0 + qq) * HIDN + d0;
        *reinterpret_cast<uint4*>(Oh + ooff) = make_uint4(hw[0], hw[1], hw[2], hw[3]);
        *reinterpret_cast<uint4*>(Ol + ooff) = make_uint4(lw[0], lw[1], lw[2], lw[3]);
    }
}

// ================= launch =================
extern "C" void kernel_launch(void* const* d_in, const int* in_sizes, int n_in,
                              void* d_out, int out_size)
{
    const float* X  = (const float*)d_in[0];
    const float* Wq = (const float*)d_in[1];
    const float* bq = (const float*)d_in[2];
    const float* Wk = (const float*)d_in[3];
    const float* bk = (const float*)d_in[4];
    const float* Wv = (const float*)d_in[5];
    const float* bv = (const float*)d_in[6];
    const float* Wo = (const float*)d_in[7];
    const float* bo = (const float*)d_in[8];
    float* out = (float*)d_out;

    float *Q, *K, *V;
    __nv_bfloat16 *Xh, *Xl, *Oh, *Ol, *Wh, *Wl;
    cudaGetSymbolAddress((void**)&Q, g_Q);
    cudaGetSymbolAddress((void**)&K, g_K);
    cudaGetSymbolAddress((void**)&V, g_V);
    cudaGetSymbolAddress((void**)&Xh, g_Xh);
    cudaGetSymbolAddress((void**)&Xl, g_Xl);
    cudaGetSymbolAddress((void**)&Oh, g_Oh);
    cudaGetSymbolAddress((void**)&Ol, g_Ol);
    cudaGetSymbolAddress((void**)&Wh, g_Wh);
    cudaGetSymbolAddress((void**)&Wl, g_Wl);

    const int attn_smem = (131 * KT_STRIDE + 64 * SC_STRIDE + 64) * (int)sizeof(float);
    cudaFuncSetAttribute(attn_blk_kernel, cudaFuncAttributeMaxDynamicSharedMemorySize, attn_smem);
    cudaFuncSetAttribute(gemm_mma_kernel, cudaFuncAttributeMaxDynamicSharedMemorySize, GEMM_SMEM);

    const int nX4 = MROWS * HIDN / 4;
    const int nW4 = HIDN * HIDN / 4;
    split_kernel<<<nX4 / 256, 256>>>(X, Xh, Xl, nX4);
    split_w_kernel<<<dim3(nW4 / 256, 4), 256>>>(Wq, Wk, Wv, Wo, Wh, Wl);

    const dim3 qkvGrid(HIDN / 128, MROWS / 128, 3);   // (8, 32, 3)
    gemm_mma_kernel<<<qkvGrid, 256, GEMM_SMEM>>>(Xh, Xl, Wh, Wl, 0, bq, bk, bv, Q, K, V);

    const dim3 attnGrid(SQ / 64, NHD, BZ);            // (32, 16, 2)
    attn_blk_kernel<<<attnGrid, 128, attn_smem>>>(Q, K, V, Oh, Ol);

    const dim3 oGrid(HIDN / 128, MROWS / 128, 1);
    gemm_mma_kernel<<<oGrid, 256, GEMM_SMEM>>>(Oh, Ol, Wh, Wl, 3, bo, bo, bo, out, out, out);
}

// round 16
// speedup vs baseline: 1.1164x; 1.0403x over previous
#include <cuda_runtime.h>
#include <cuda_bf16.h>
#include <cstdint>
#include <math.h>

// ---------------- problem constants ----------------
#define BZ   2
#define SQ   2048
#define HIDN 1024
#define NHD  16
#define HDIM 64
#define MROWS (BZ * SQ)      // 4096
#define WIN  64              // LOCAL_WINDOW / 2

// ---------------- scratch (no allocations allowed) ----------------
__device__ float g_Q[MROWS * HIDN];
__device__ float g_K[MROWS * HIDN];
__device__ float g_V[MROWS * HIDN];
__device__ __nv_bfloat16 g_Xh[MROWS * HIDN];
__device__ __nv_bfloat16 g_Xl[MROWS * HIDN];
__device__ __nv_bfloat16 g_Oh[MROWS * HIDN];
__device__ __nv_bfloat16 g_Ol[MROWS * HIDN];
__device__ __nv_bfloat16 g_Wh[4][HIDN * HIDN];
__device__ __nv_bfloat16 g_Wl[4][HIDN * HIDN];

// ================= helpers =================
__device__ __forceinline__ uint32_t smem_u32(const void* p) {
    uint32_t a;
    asm("{ .reg .u64 t; cvta.to.shared.u64 t, %1; cvt.u32.u64 %0, t; }" : "=r"(a) : "l"(p));
    return a;
}
#define CP_ASYNC16(sm, gm) \
    asm volatile("cp.async.cg.shared.global [%0], [%1], 16;" :: "r"(sm), "l"(gm) : "memory")
#define CP_COMMIT() asm volatile("cp.async.commit_group;" ::: "memory")
#define CP_WAIT1()  asm volatile("cp.async.wait_group 1;" ::: "memory")
#define CP_WAIT0()  asm volatile("cp.async.wait_group 0;" ::: "memory")

#define LDSM_X4(r0, r1, r2, r3, addr) \
    asm volatile("ldmatrix.sync.aligned.m8n8.x4.shared.b16 {%0,%1,%2,%3}, [%4];" \
        : "=r"(r0), "=r"(r1), "=r"(r2), "=r"(r3) : "r"(addr))

#define MMA_BF16(d, a, b) \
    asm volatile("mma.sync.aligned.m16n8k16.row.col.f32.bf16.bf16.f32 " \
        "{%0,%1,%2,%3}, {%4,%5,%6,%7}, {%8,%9}, {%0,%1,%2,%3};" \
        : "+f"((d)[0]), "+f"((d)[1]), "+f"((d)[2]), "+f"((d)[3]) \
        : "r"((a)[0]), "r"((a)[1]), "r"((a)[2]), "r"((a)[3]), "r"((b)[0]), "r"((b)[1]))

// ================= fp32 -> (bf16 hi, bf16 lo) split =================
__device__ __forceinline__ void split4(const float* __restrict__ src,
                                       __nv_bfloat16* __restrict__ hi,
                                       __nv_bfloat16* __restrict__ lo, int i) {
    float4 v = reinterpret_cast<const float4*>(src)[i];
    __nv_bfloat16 h0 = __float2bfloat16(v.x), h1 = __float2bfloat16(v.y);
    __nv_bfloat16 h2 = __float2bfloat16(v.z), h3 = __float2bfloat16(v.w);
    __nv_bfloat16 l0 = __float2bfloat16(v.x - __bfloat162float(h0));
    __nv_bfloat16 l1 = __float2bfloat16(v.y - __bfloat162float(h1));
    __nv_bfloat16 l2 = __float2bfloat16(v.z - __bfloat162float(h2));
    __nv_bfloat16 l3 = __float2bfloat16(v.w - __bfloat162float(h3));
    __nv_bfloat162 hA = __halves2bfloat162(h0, h1), hB = __halves2bfloat162(h2, h3);
    __nv_bfloat162 lA = __halves2bfloat162(l0, l1), lB = __halves2bfloat162(l2, l3);
    uint2 ho, lout;
    ho.x = *reinterpret_cast<uint32_t*>(&hA); ho.y = *reinterpret_cast<uint32_t*>(&hB);
    lout.x = *reinterpret_cast<uint32_t*>(&lA); lout.y = *reinterpret_cast<uint32_t*>(&lB);
    reinterpret_cast<uint2*>(hi)[i] = ho;
    reinterpret_cast<uint2*>(lo)[i] = lout;
}

// merged: grid.y = 0 -> X (n4 = 1M), grid.y in 1..4 -> weight (grid.y-1), n4 = 256K
__global__ __launch_bounds__(256) void split_all_kernel(
    const float* __restrict__ X,
    const float* __restrict__ w0, const float* __restrict__ w1,
    const float* __restrict__ w2, const float* __restrict__ w3,
    __nv_bfloat16* __restrict__ Xh, __nv_bfloat16* __restrict__ Xl,
    __nv_bfloat16* __restrict__ WhBase, __nv_bfloat16* __restrict__ WlBase)
{
    const int which = blockIdx.y;
    int i = blockIdx.x * 256 + threadIdx.x;
    if (which == 0) {
        if (i < MROWS * HIDN / 4) split4(X, Xh, Xl, i);
    } else {
        if (i < HIDN * HIDN / 4) {
            const float* src = (which == 1) ? w0 : (which == 2) ? w1 : (which == 3) ? w2 : w3;
            split4(src, WhBase + (size_t)(which - 1) * HIDN * HIDN,
                        WlBase + (size_t)(which - 1) * HIDN * HIDN, i);
        }
    }
}

// ================= mma.sync bf16x3 GEMM, fused-term stages (R10 exact, proven 418us) =================
#define GPITCH_B 80u          // bytes per smem row
#define MBUFB    10240u       // one matrix per stage: 128 * 80
#define GSTGB    40960u       // 4 matrices per stage
#define GSTAGES  32           // 1024 / 32
#define GEMM_SMEM (2 * GSTGB) // 81920 (2-stage ring)

__global__ __launch_bounds__(256, 2) void gemm_mma_kernel(
    const __nv_bfloat16* __restrict__ Ah, const __nv_bfloat16* __restrict__ Al,
    const __nv_bfloat16* __restrict__ Whb, const __nv_bfloat16* __restrict__ Wlb,
    int wbase,
    const float* __restrict__ b0, const float* __restrict__ b1, const float* __restrict__ b2,
    float* __restrict__ C0, float* __restrict__ C1, float* __restrict__ C2)
{
    extern __shared__ __align__(16) char gsm[];

    const int z = blockIdx.z;
    const __nv_bfloat16* Bh = Whb + (size_t)(wbase + z) * HIDN * HIDN;
    const __nv_bfloat16* Bl = Wlb + (size_t)(wbase + z) * HIDN * HIDN;
    const float* bias = (z == 0) ? b0 : (z == 1) ? b1 : b2;
    float* C = (z == 0) ? C0 : (z == 1) ? C1 : C2;

    const int tid = threadIdx.x;
    const int wid = tid >> 5;
    const int lane = tid & 31;
    const int wm = wid & 1;          // warp row 0..1 (64 rows each)
    const int wn = wid >> 1;         // warp col 0..3 (32 cols each)
    const int m0 = blockIdx.y * 128;
    const int n0 = blockIdx.x * 128;

    const uint32_t smBase = smem_u32(gsm);

    const int lrow = tid >> 2;       // 0..63
    const int lchk = tid & 3;

    float acc[4][4][4];
    #pragma unroll
    for (int mi = 0; mi < 4; ++mi)
        #pragma unroll
        for (int j = 0; j < 4; ++j)
            #pragma unroll
            for (int r = 0; r < 4; ++r) acc[mi][j][r] = 0.f;

    auto issue_stage = [&](int s) {
        const int kk = s << 5;
        const uint32_t sbase = smBase + (uint32_t)(s & 1) * GSTGB;
        #pragma unroll
        for (int u = 0; u < 2; ++u) {
            const int r = u * 64 + lrow;
            const uint32_t so = (uint32_t)r * GPITCH_B + (uint32_t)lchk * 16u;
            const size_t ga = (size_t)(m0 + r) * HIDN + kk + lchk * 8;
            const size_t gb = (size_t)(n0 + r) * HIDN + kk + lchk * 8;
            CP_ASYNC16(sbase + so,              Ah + ga);
            CP_ASYNC16(sbase + MBUFB + so,      Al + ga);
            CP_ASYNC16(sbase + 2 * MBUFB + so,  Bh + gb);
            CP_ASYNC16(sbase + 3 * MBUFB + so,  Bl + gb);
        }
    };

    issue_stage(0); CP_COMMIT();
    issue_stage(1); CP_COMMIT();

    const uint32_t aFragOff = (uint32_t)((wm * 64 + (lane & 15)) * GPITCH_B + ((lane >> 4) & 1) * 16);
    const uint32_t bFragOff = (uint32_t)((wn * 32 + (lane & 7) + ((lane >> 1) & 8)) * GPITCH_B
                                         + ((lane & 8) ? 16 : 0));

    for (int s = 0; s < GSTAGES; ++s) {
        if (s + 1 < GSTAGES) CP_WAIT1(); else CP_WAIT0();
        __syncthreads();

        const uint32_t sbase = smBase + (uint32_t)(s & 1) * GSTGB;
        const uint32_t aHB = sbase + aFragOff;
        const uint32_t aLB = sbase + MBUFB + aFragOff;
        const uint32_t bHB = sbase + 2 * MBUFB + bFragOff;
        const uint32_t bLB = sbase + 3 * MBUFB + bFragOff;

        #pragma unroll
        for (int ks = 0; ks < 2; ++ks) {
            uint32_t ah[4][4];
            #pragma unroll
            for (int mi = 0; mi < 4; ++mi)
                LDSM_X4(ah[mi][0], ah[mi][1], ah[mi][2], ah[mi][3],
                        aHB + mi * 16 * GPITCH_B + ks * 32);
            uint32_t bh[4][2];
            LDSM_X4(bh[0][0], bh[0][1], bh[1][0], bh[1][1], bHB + ks * 32);
            LDSM_X4(bh[2][0], bh[2][1], bh[3][0], bh[3][1], bHB + 16 * GPITCH_B + ks * 32);
            uint32_t bl[4][2];
            LDSM_X4(bl[0][0], bl[0][1], bl[1][0], bl[1][1], bLB + ks * 32);
            LDSM_X4(bl[2][0], bl[2][1], bl[3][0], bl[3][1], bLB + 16 * GPITCH_B + ks * 32);

            #pragma unroll
            for (int mi = 0; mi < 4; ++mi)
                #pragma unroll
                for (int j = 0; j < 4; ++j)
                    MMA_BF16(acc[mi][j], ah[mi], bh[j]);   // Ah*Bh
            #pragma unroll
            for (int mi = 0; mi < 4; ++mi)
                #pragma unroll
                for (int j = 0; j < 4; ++j)
                    MMA_BF16(acc[mi][j], ah[mi], bl[j]);   // Ah*Bl

            uint32_t al[4][4];
            #pragma unroll
            for (int mi = 0; mi < 4; ++mi)
                LDSM_X4(al[mi][0], al[mi][1], al[mi][2], al[mi][3],
                        aLB + mi * 16 * GPITCH_B + ks * 32);
            #pragma unroll
            for (int mi = 0; mi < 4; ++mi)
                #pragma unroll
                for (int j = 0; j < 4; ++j)
                    MMA_BF16(acc[mi][j], al[mi], bh[j]);   // Al*Bh
        }
        __syncthreads();
        if (s + 2 < GSTAGES) { issue_stage(s + 2); CP_COMMIT(); }
    }

    // ---- epilogue ----
    const int g = lane >> 2, t = lane & 3;
    float2 bv[4];
    #pragma unroll
    for (int j = 0; j < 4; ++j) {
        const int col = n0 + wn * 32 + j * 8 + t * 2;
        bv[j].x = __ldg(bias + col);
        bv[j].y = __ldg(bias + col + 1);
    }
    #pragma unroll
    for (int mi = 0; mi < 4; ++mi) {
        const int row0 = m0 + wm * 64 + mi * 16 + g;
        #pragma unroll
        for (int j = 0; j < 4; ++j) {
            const int col = n0 + wn * 32 + j * 8 + t * 2;
            float2 o0 = { acc[mi][j][0] + bv[j].x, acc[mi][j][1] + bv[j].y };
            float2 o1 = { acc[mi][j][2] + bv[j].x, acc[mi][j][3] + bv[j].y };
            *reinterpret_cast<float2*>(C + (size_t)row0 * HIDN + col) = o0;
            *reinterpret_cast<float2*>(C + (size_t)(row0 + 8) * HIDN + col) = o1;
        }
    }
}

// ================= query-block sparse attention (R10 + row-loop unrolling) =================
#define KT_STRIDE 68
#define SC_STRIDE 67

__global__ __launch_bounds__(128) void attn_blk_kernel(
    const float* __restrict__ Q, const float* __restrict__ K,
    const float* __restrict__ V,
    __nv_bfloat16* __restrict__ Oh, __nv_bfloat16* __restrict__ Ol)
{
    extern __shared__ float sm[];
    float* Kt   = sm;                              // [131][68]
    float* Sc   = sm + 131 * KT_STRIDE;            // [64][67]
    float* Sinv = Sc + 64 * SC_STRIDE;             // [64]

    const int qb = blockIdx.x, h = blockIdx.y, b = blockIdx.z;
    const int i0 = qb * 64;
    const int jlo = (i0 > 64) ? (i0 - 64) : 0;
    const int nrows = i0 + 63 - jlo + 1;
    const bool extraG = (jlo > 0);
    const int grow = extraG ? 130 : 0;
    const int tid = threadIdx.x;
    const size_t base = (size_t)b * SQ * HIDN + (size_t)h * HDIM;

    for (int idx = tid; idx < nrows * 16; idx += 128) {
        int r = idx >> 4, c = idx & 15;
        float4 v = *reinterpret_cast<const float4*>(K + base + (size_t)(jlo + r) * HIDN + c * 4);
        *reinterpret_cast<float4*>(Kt + r * KT_STRIDE + c * 4) = v;
    }
    if (extraG && tid < 16) {
        float4 v = *reinterpret_cast<const float4*>(K + base + tid * 4);
        *reinterpret_cast<float4*>(Kt + 130 * KT_STRIDE + tid * 4) = v;
    }

    const int qg = tid >> 3;
    const int part = tid & 7;
    const int d0 = part * 8;
    const int iq0 = i0 + qg * 4;

    int r0q[4], nwq[4];
    #pragma unroll
    for (int qq = 0; qq < 4; ++qq) {
        const int iq = iq0 + qq;
        const int wloq = (iq > 64) ? (iq - 64) : 0;
        r0q[qq] = wloq - jlo;
        nwq[qq] = iq - wloq + 1;
    }

    float qr[4][8];
    #pragma unroll
    for (int qq = 0; qq < 4; ++qq) {
        const float* qp = Q + base + (size_t)(iq0 + qq) * HIDN + d0;
        float4 a = *reinterpret_cast<const float4*>(qp);
        float4 c = *reinterpret_cast<const float4*>(qp + 4);
        qr[qq][0] = a.x; qr[qq][1] = a.y; qr[qq][2] = a.z; qr[qq][3] = a.w;
        qr[qq][4] = c.x; qr[qq][5] = c.y; qr[qq][6] = c.z; qr[qq][7] = c.w;
    }
    __syncthreads();

    const int wq = tid >> 5;
    const int iFirst = i0 + wq * 16;
    const int iLast = iFirst + 15;
    const int rbeg = ((iFirst > 64) ? (iFirst - 64) : 0) - jlo;
    const int rend = iLast - jlo + 1;

    // ---- scores: unrolled x4 -> 16 independent dot/shuffle chains in flight ----
    #pragma unroll 4
    for (int row = rbeg; row < rend; ++row) {
        const float* kp = Kt + row * KT_STRIDE + d0;
        float4 k0 = *reinterpret_cast<const float4*>(kp);
        float4 k1 = *reinterpret_cast<const float4*>(kp + 4);
        #pragma unroll
        for (int qq = 0; qq < 4; ++qq) {
            float dot = qr[qq][0] * k0.x;
            dot = fmaf(qr[qq][1], k0.y, dot); dot = fmaf(qr[qq][2], k0.z, dot);
            dot = fmaf(qr[qq][3], k0.w, dot); dot = fmaf(qr[qq][4], k1.x, dot);
            dot = fmaf(qr[qq][5], k1.y, dot); dot = fmaf(qr[qq][6], k1.z, dot);
            dot = fmaf(qr[qq][7], k1.w, dot);
            dot += __shfl_xor_sync(0xffffffffu, dot, 1);
            dot += __shfl_xor_sync(0xffffffffu, dot, 2);
            dot += __shfl_xor_sync(0xffffffffu, dot, 4);
            const int s = row - r0q[qq];
            if (part == 0 && s >= 0 && s < nwq[qq])
                Sc[(qg * 4 + qq) * SC_STRIDE + s] = dot * 0.125f;
        }
    }
    {
        const float* kp = Kt + grow * KT_STRIDE + d0;
        float4 k0 = *reinterpret_cast<const float4*>(kp);
        float4 k1 = *reinterpret_cast<const float4*>(kp + 4);
        #pragma unroll
        for (int qq = 0; qq < 4; ++qq) {
            float dot = qr[qq][0] * k0.x;
            dot = fmaf(qr[qq][1], k0.y, dot); dot = fmaf(qr[qq][2], k0.z, dot);
            dot = fmaf(qr[qq][3], k0.w, dot); dot = fmaf(qr[qq][4], k1.x, dot);
            dot = fmaf(qr[qq][5], k1.y, dot); dot = fmaf(qr[qq][6], k1.z, dot);
            dot = fmaf(qr[qq][7], k1.w, dot);
            dot += __shfl_xor_sync(0xffffffffu, dot, 1);
            dot += __shfl_xor_sync(0xffffffffu, dot, 2);
            dot += __shfl_xor_sync(0xffffffffu, dot, 4);
            if (part == 0 && (iq0 + qq) > 64)
                Sc[(qg * 4 + qq) * SC_STRIDE + nwq[qq]] = dot * 0.125f;
        }
    }
    __syncthreads();

    for (int idx = tid; idx < nrows * 16; idx += 128) {
        int r = idx >> 4, c = idx & 15;
        float4 v = *reinterpret_cast<const float4*>(V + base + (size_t)(jlo + r) * HIDN + c * 4);
        *reinterpret_cast<float4*>(Kt + r * KT_STRIDE + c * 4) = v;
    }
    if (extraG && tid < 16) {
        float4 v = *reinterpret_cast<const float4*>(V + base + tid * 4);
        *reinterpret_cast<float4*>(Kt + 130 * KT_STRIDE + tid * 4) = v;
    }

    if (tid < 64) {
        const int iq = i0 + tid;
        const int wloq = (iq > 64) ? (iq - 64) : 0;
        const int nsq = (iq - wloq + 1) + ((wloq > 0) ? 1 : 0);
        float* sc = Sc + tid * SC_STRIDE;
        float m = -1e30f;
        for (int s = 0; s < nsq; ++s) m = fmaxf(m, sc[s]);
        float sum = 0.f;
        for (int s = 0; s < nsq; ++s) { float e = __expf(sc[s] - m); sc[s] = e; sum += e; }
        Sinv[tid] = 1.f / sum;
    }
    __syncthreads();

    float acc[4][8];
    #pragma unroll
    for (int qq = 0; qq < 4; ++qq)
        #pragma unroll
        for (int d = 0; d < 8; ++d) acc[qq][d] = 0.f;

    #pragma unroll 4
    for (int row = rbeg; row < rend; ++row) {
        const float* vp = Kt + row * KT_STRIDE + d0;
        float4 v0 = *reinterpret_cast<const float4*>(vp);
        float4 v1 = *reinterpret_cast<const float4*>(vp + 4);
        #pragma unroll
        for (int qq = 0; qq < 4; ++qq) {
            const int s = row - r0q[qq];
            const bool ok = (s >= 0 && s < nwq[qq]);
            float pr = ok ? Sc[(qg * 4 + qq) * SC_STRIDE + (ok ? s : 0)] : 0.f;
            acc[qq][0] = fmaf(pr, v0.x, acc[qq][0]); acc[qq][1] = fmaf(pr, v0.y, acc[qq][1]);
            acc[qq][2] = fmaf(pr, v0.z, acc[qq][2]); acc[qq][3] = fmaf(pr, v0.w, acc[qq][3]);
            acc[qq][4] = fmaf(pr, v1.x, acc[qq][4]); acc[qq][5] = fmaf(pr, v1.y, acc[qq][5]);
            acc[qq][6] = fmaf(pr, v1.z, acc[qq][6]); acc[qq][7] = fmaf(pr, v1.w, acc[qq][7]);
        }
    }
    {
        const float* vp = Kt + grow * KT_STRIDE + d0;
        float4 v0 = *reinterpret_cast<const float4*>(vp);
        float4 v1 = *reinterpret_cast<const float4*>(vp + 4);
        #pragma unroll
        for (int qq = 0; qq < 4; ++qq) {
            float pr = ((iq0 + qq) > 64) ? Sc[(qg * 4 + qq) * SC_STRIDE + nwq[qq]] : 0.f;
            acc[qq][0] = fmaf(pr, v0.x, acc[qq][0]); acc[qq][1] = fmaf(pr, v0.y, acc[qq][1]);
            acc[qq][2] = fmaf(pr, v0.z, acc[qq][2]); acc[qq][3] = fmaf(pr, v0.w, acc[qq][3]);
            acc[qq][4] = fmaf(pr, v1.x, acc[qq][4]); acc[qq][5] = fmaf(pr, v1.y, acc[qq][5]);
            acc[qq][6] = fmaf(pr, v1.z, acc[qq][6]); acc[qq][7] = fmaf(pr, v1.w, acc[qq][7]);
        }
    }

    #pragma unroll
    for (int qq = 0; qq < 4; ++qq) {
        const float si = Sinv[qg * 4 + qq];
        uint32_t hw[4], lw[4];
        #pragma unroll
        for (int d = 0; d < 8; d += 2) {
            float v0 = acc[qq][d] * si, v1 = acc[qq][d + 1] * si;
            __nv_bfloat16 h0 = __float2bfloat16(v0), h1 = __float2bfloat16(v1);
            __nv_bfloat16 l0 = __float2bfloat16(v0 - __bfloat162float(h0));
            __nv_bfloat16 l1 = __float2bfloat16(v1 - __bfloat162float(h1));
            __nv_bfloat162 hp = __halves2bfloat162(h0, h1);
            __nv_bfloat162 lp = __halves2bfloat162(l0, l1);
            hw[d >> 1] = *reinterpret_cast<uint32_t*>(&hp);
            lw[d >> 1] = *reinterpret_cast<uint32_t*>(&lp);
        }
        const size_t ooff = base + (size_t)(iq0 + qq) * HIDN + d0;
        *reinterpret_cast<uint4*>(Oh + ooff) = make_uint4(hw[0], hw[1], hw[2], hw[3]);
        *reinterpret_cast<uint4*>(Ol + ooff) = make_uint4(lw[0], lw[1], lw[2], lw[3]);
    }
}

// ================= launch =================
extern "C" void kernel_launch(void* const* d_in, const int* in_sizes, int n_in,
                              void* d_out, int out_size)
{
    const float* X  = (const float*)d_in[0];
    const float* Wq = (const float*)d_in[1];
    const float* bq = (const float*)d_in[2];
    const float* Wk = (const float*)d_in[3];
    const float* bk = (const float*)d_in[4];
    const float* Wv = (const float*)d_in[5];
    const float* bv = (const float*)d_in[6];
    const float* Wo = (const float*)d_in[7];
    const float* bo = (const float*)d_in[8];
    float* out = (float*)d_out;

    float *Q, *K, *V;
    __nv_bfloat16 *Xh, *Xl, *Oh, *Ol, *Wh, *Wl;
    cudaGetSymbolAddress((void**)&Q, g_Q);
    cudaGetSymbolAddress((void**)&K, g_K);
    cudaGetSymbolAddress((void**)&V, g_V);
    cudaGetSymbolAddress((void**)&Xh, g_Xh);
    cudaGetSymbolAddress((void**)&Xl, g_Xl);
    cudaGetSymbolAddress((void**)&Oh, g_Oh);
    cudaGetSymbolAddress((void**)&Ol, g_Ol);
    cudaGetSymbolAddress((void**)&Wh, g_Wh);
    cudaGetSymbolAddress((void**)&Wl, g_Wl);

    const int attn_smem = (131 * KT_STRIDE + 64 * SC_STRIDE + 64) * (int)sizeof(float);
    cudaFuncSetAttribute(attn_blk_kernel, cudaFuncAttributeMaxDynamicSharedMemorySize, attn_smem);
    cudaFuncSetAttribute(gemm_mma_kernel, cudaFuncAttributeMaxDynamicSharedMemorySize, GEMM_SMEM);

    const int nX4 = MROWS * HIDN / 4;                 // 1,048,576 -> 4096 blocks
    split_all_kernel<<<dim3(nX4 / 256, 5), 256>>>(X, Wq, Wk, Wv, Wo, Xh, Xl, Wh, Wl);

    const dim3 qkvGrid(HIDN / 128, MROWS / 128, 3);   // (8, 32, 3)
    gemm_mma_kernel<<<qkvGrid, 256, GEMM_SMEM>>>(Xh, Xl, Wh, Wl, 0, bq, bk, bv, Q, K, V);

    const dim3 attnGrid(SQ / 64, NHD, BZ);            // (32, 16, 2)
    attn_blk_kernel<<<attnGrid, 128, attn_smem>>>(Q, K, V, Oh, Ol);

    const dim3 oGrid(HIDN / 128, MROWS / 128, 1);
    gemm_mma_kernel<<<oGrid, 256, GEMM_SMEM>>>(Oh, Ol, Wh, Wl, 3, bo, bo, bo, out, out, out);
}